// round 4
// baseline (speedup 1.0000x reference)
#include <cuda_runtime.h>
#include <math.h>
#include <stdint.h>

#define S_ 7
#define H_ 56
#define W_ 56
#define WS 7
#define C_ 384
#define HEADS 12
#define NW 64
#define NTOK 344
#define NWIN 343
#define L_ (S_*H_*W_)          /* 21952 */
#define M1 (NW*NTOK)           /* 22016 */
#define HID 1536
#define EPS_LN 1e-5f
#define QSCALE 0.17677669529663687f  /* 32^-0.5 */

/* ---------------- scratch (static device globals; no allocation) -------- */
__device__ float g_xc     [(size_t)M1 * C_];        /* LN1'd windows + gt   */
__device__ float g_qkv    [(size_t)M1 * 3 * C_];
__device__ float g_attnout[(size_t)M1 * C_];
__device__ float g_proj   [(size_t)M1 * C_];
__device__ float g_xres   [(size_t)L_ * C_];
__device__ float g_ln2    [(size_t)L_ * C_];
__device__ float g_hid    [(size_t)L_ * HID];
__device__ float g_bias   [(size_t)HEADS * NWIN * NWIN];

/* ---------------- helpers ---------------------------------------------- */
__device__ __forceinline__ float warp_sum(float v) {
    v += __shfl_xor_sync(0xffffffffu, v, 16);
    v += __shfl_xor_sync(0xffffffffu, v, 8);
    v += __shfl_xor_sync(0xffffffffu, v, 4);
    v += __shfl_xor_sync(0xffffffffu, v, 2);
    v += __shfl_xor_sync(0xffffffffu, v, 1);
    return v;
}
__device__ __forceinline__ float warp_max(float v) {
    v = fmaxf(v, __shfl_xor_sync(0xffffffffu, v, 16));
    v = fmaxf(v, __shfl_xor_sync(0xffffffffu, v, 8));
    v = fmaxf(v, __shfl_xor_sync(0xffffffffu, v, 4));
    v = fmaxf(v, __shfl_xor_sync(0xffffffffu, v, 2));
    v = fmaxf(v, __shfl_xor_sync(0xffffffffu, v, 1));
    return v;
}
__device__ __forceinline__ float gelu_f(float v) {
    return 0.5f * v * (1.f + erff(v * 0.7071067811865475f));
}
/* original token l -> row in windowed layout (after roll by -3 and window
   partition). Same map is used for the inverse (roll +3 then gather). */
__device__ __forceinline__ int scatter_row(int l) {
    int s   = l / (H_ * W_);
    int rem = l % (H_ * W_);
    int h   = rem / W_;
    int w   = rem % W_;
    int s2 = (s >= 3) ? s - 3 : s + 4;
    int h2 = (h >= 3) ? h - 3 : h + 53;
    int w2 = (w >= 3) ? w - 3 : w + 53;
    int win = (h2 / WS) * 8 + (w2 / WS);
    int t   = s2 * 49 + (h2 % WS) * 7 + (w2 % WS);
    return win * NTOK + 1 + t;
}

/* ---------------- small kernels ----------------------------------------- */
__global__ void bias_pre(const float* __restrict__ bt) {
    int idx = blockIdx.x * blockDim.x + threadIdx.x;
    if (idx >= NWIN * NWIN) return;
    int i = idx / NWIN, j = idx % NWIN;
    int si = i / 49, hi = (i / 7) % 7, wi = i % 7;
    int sj = j / 49, hj = (j / 7) % 7, wj = j % 7;
    int r = (si - sj + 6) * 20 + (hi - hj + 6) * 13 + (wi - wj + 6);
#pragma unroll
    for (int h = 0; h < HEADS; h++)
        g_bias[(size_t)h * NWIN * NWIN + idx] = bt[r * HEADS + h];
}

__global__ void gt_copy(const float* __restrict__ gt) {
    int idx = blockIdx.x * blockDim.x + threadIdx.x;
    if (idx >= NW * C_) return;
    int w = idx / C_, c = idx % C_;
    g_xc[((size_t)w * NTOK) * C_ + c] = gt[idx];
}

__global__ void gt_out_copy(float* __restrict__ out) {
    int idx = blockIdx.x * blockDim.x + threadIdx.x;
    if (idx >= NW * C_) return;
    int w = idx / C_, c = idx % C_;
    out[(size_t)L_ * C_ + idx] = g_proj[((size_t)w * NTOK) * C_ + c];
}

__global__ void ln1_scatter(const float* __restrict__ x,
                            const float* __restrict__ g,
                            const float* __restrict__ b) {
    int gw   = (blockIdx.x * blockDim.x + threadIdx.x) >> 5;
    int lane = threadIdx.x & 31;
    if (gw >= L_) return;
    const float* xi = x + (size_t)gw * C_;
    float v[12];
    float sum = 0.f;
#pragma unroll
    for (int m = 0; m < 12; m++) { v[m] = xi[lane + m * 32]; sum += v[m]; }
    sum = warp_sum(sum);
    float mu = sum * (1.f / 384.f);
    float vs = 0.f;
#pragma unroll
    for (int m = 0; m < 12; m++) { float d = v[m] - mu; vs += d * d; }
    vs = warp_sum(vs);
    float rstd = rsqrtf(vs * (1.f / 384.f) + EPS_LN);
    float* o = g_xc + (size_t)scatter_row(gw) * C_;
#pragma unroll
    for (int m = 0; m < 12; m++) {
        int c = lane + m * 32;
        o[c] = (v[m] - mu) * rstd * g[c] + b[c];
    }
}

__global__ void ln2_kernel(const float* __restrict__ g,
                           const float* __restrict__ b) {
    int gw   = (blockIdx.x * blockDim.x + threadIdx.x) >> 5;
    int lane = threadIdx.x & 31;
    if (gw >= L_) return;
    const float* xi = g_xres + (size_t)gw * C_;
    float v[12];
    float sum = 0.f;
#pragma unroll
    for (int m = 0; m < 12; m++) { v[m] = xi[lane + m * 32]; sum += v[m]; }
    sum = warp_sum(sum);
    float mu = sum * (1.f / 384.f);
    float vs = 0.f;
#pragma unroll
    for (int m = 0; m < 12; m++) { float d = v[m] - mu; vs += d * d; }
    vs = warp_sum(vs);
    float rstd = rsqrtf(vs * (1.f / 384.f) + EPS_LN);
    float* o = g_ln2 + (size_t)gw * C_;
#pragma unroll
    for (int m = 0; m < 12; m++) {
        int c = lane + m * 32;
        o[c] = (v[m] - mu) * rstd * g[c] + b[c];
    }
}

__global__ void unscatter_res(const float* __restrict__ x) {
    int idx = blockIdx.x * blockDim.x + threadIdx.x;
    if (idx >= L_ * C_) return;
    int l = idx / C_, c = idx % C_;
    g_xres[idx] = x[idx] + g_proj[(size_t)scatter_row(l) * C_ + c];
}

/* ---------------- fused attention: one block per (window, head) --------- */
#define KSTRIDE 36
#define ATT_SMEM_BYTES ((NTOK*KSTRIDE*2 + 8*NTOK + 8*32) * 4 + NTOK * 4)

__global__ __launch_bounds__(256) void attn_kernel() {
    extern __shared__ float sm[];
    float* Ks = sm;                       /* 344*36 */
    float* Vs = Ks + NTOK * KSTRIDE;      /* 344*36 */
    float* Ps = Vs + NTOK * KSTRIDE;      /* 8*344  */
    float* Qs = Ps + 8 * NTOK;            /* 8*32   */
    int*  lab = (int*)(Qs + 8 * 32);      /* 344    */

    int tid = threadIdx.x, wid = tid >> 5, lane = tid & 31;
    int win = blockIdx.x / HEADS, head = blockIdx.x % HEADS;
    const float* base = g_qkv + (size_t)win * NTOK * (3 * C_) + head * 32;

    for (int idx = tid; idx < NTOK * 32; idx += 256) {
        int j = idx >> 5, dd = idx & 31;
        size_t ro = (size_t)j * (3 * C_);
        Ks[j * KSTRIDE + dd] = base[ro + C_ + dd];
        Vs[j * KSTRIDE + dd] = base[ro + 2 * C_ + dd];
    }
    int wh = win >> 3, ww = win & 7;
    for (int t = tid; t < NTOK; t += 256) {
        int lv = -1;
        if (t > 0) {
            int t0 = t - 1;
            int ts = t0 / 49, th = (t0 / 7) % 7, tw = t0 % 7;
            int hh = wh * 7 + th, wc = ww * 7 + tw;
            int ia = (ts < 4) ? 1 : 2;
            int ib = (hh < 49) ? 0 : ((hh < 53) ? 1 : 2);
            int ic = (wc < 49) ? 0 : ((wc < 53) ? 1 : 2);
            lv = ia * 9 + ib * 3 + ic;
        }
        lab[t] = lv;
    }
    __syncthreads();

    const float* bh = g_bias + (size_t)head * NWIN * NWIN;
    for (int r = wid; r < NTOK; r += 8) {
        Qs[wid * 32 + lane] = base[(size_t)r * (3 * C_) + lane] * QSCALE;
        __syncwarp();
        int lr = lab[r];
        const float4* q4 = (const float4*)(Qs + wid * 32);
        float s[11];
#pragma unroll
        for (int m = 0; m < 11; m++) {
            int j = lane + (m << 5);
            float acc;
            if (j < NTOK) {
                const float4* k4 = (const float4*)(Ks + j * KSTRIDE);
                acc = 0.f;
#pragma unroll
                for (int q = 0; q < 8; q++) {
                    float4 kk = k4[q], qq = q4[q];
                    acc += kk.x * qq.x; acc += kk.y * qq.y;
                    acc += kk.z * qq.z; acc += kk.w * qq.w;
                }
                if (r > 0 && j > 0) {
                    acc += bh[(r - 1) * NWIN + (j - 1)];
                    if (lr != lab[j]) acc -= 100.f;
                }
            } else {
                acc = -1e30f;
            }
            s[m] = acc;
        }
        float mx = s[0];
#pragma unroll
        for (int m = 1; m < 11; m++) mx = fmaxf(mx, s[m]);
        mx = warp_max(mx);
        float sum = 0.f;
#pragma unroll
        for (int m = 0; m < 11; m++) { float e = __expf(s[m] - mx); s[m] = e; sum += e; }
        sum = warp_sum(sum);
        float inv = 1.f / sum;
#pragma unroll
        for (int m = 0; m < 11; m++) {
            int j = lane + (m << 5);
            if (j < NTOK) Ps[wid * NTOK + j] = s[m] * inv;
        }
        __syncwarp();
        float o = 0.f;
        const float4* p4 = (const float4*)(Ps + wid * NTOK);
#pragma unroll 2
        for (int jq = 0; jq < NTOK / 4; jq++) {
            float4 p = p4[jq];
            int j = jq << 2;
            o += p.x * Vs[(j + 0) * KSTRIDE + lane];
            o += p.y * Vs[(j + 1) * KSTRIDE + lane];
            o += p.z * Vs[(j + 2) * KSTRIDE + lane];
            o += p.w * Vs[(j + 3) * KSTRIDE + lane];
        }
        g_attnout[((size_t)win * NTOK + r) * C_ + head * 32 + lane] = o;
        __syncwarp();
    }
}

/* ---------------- SGEMM: C = A[MxK] @ B[KxN] + bias, epilogue ----------- */
/* EPI: 0 = none, 1 = gelu, 2 = + res                                      */
template<int EPI>
__global__ __launch_bounds__(256) void sgemm(const float* __restrict__ A,
                                             const float* __restrict__ B,
                                             const float* __restrict__ bias,
                                             const float* __restrict__ res,
                                             float* __restrict__ Cd,
                                             int M, int N, int K) {
    __shared__ float As[16][64];
    __shared__ float Bs[16][64];
    int tid = threadIdx.x;
    int tx = tid & 15, ty = tid >> 4;
    int ar = tid >> 2, ac = (tid & 3) << 2;
    int br = tid >> 4, bc = (tid & 15) << 2;
    const float* Ap = A + (size_t)(blockIdx.y * 64 + ar) * K + ac;
    const float* Bp = B + (size_t)br * N + blockIdx.x * 64 + bc;
    float acc[4][4] = {};
    for (int kt = 0; kt < K; kt += 16) {
        float4 av = *(const float4*)(Ap + kt);
        float4 bv = *(const float4*)(Bp + (size_t)kt * N);
        As[ac + 0][ar] = av.x; As[ac + 1][ar] = av.y;
        As[ac + 2][ar] = av.z; As[ac + 3][ar] = av.w;
        *(float4*)&Bs[br][bc] = bv;
        __syncthreads();
#pragma unroll
        for (int k = 0; k < 16; k++) {
            float4 a = *(const float4*)&As[k][ty << 2];
            float4 b = *(const float4*)&Bs[k][tx << 2];
            acc[0][0] += a.x * b.x; acc[0][1] += a.x * b.y;
            acc[0][2] += a.x * b.z; acc[0][3] += a.x * b.w;
            acc[1][0] += a.y * b.x; acc[1][1] += a.y * b.y;
            acc[1][2] += a.y * b.z; acc[1][3] += a.y * b.w;
            acc[2][0] += a.z * b.x; acc[2][1] += a.z * b.y;
            acc[2][2] += a.z * b.z; acc[2][3] += a.z * b.w;
            acc[3][0] += a.w * b.x; acc[3][1] += a.w * b.y;
            acc[3][2] += a.w * b.z; acc[3][3] += a.w * b.w;
        }
        __syncthreads();
    }
    int col = blockIdx.x * 64 + (tx << 2);
    float4 bb = *(const float4*)&bias[col];
#pragma unroll
    for (int i = 0; i < 4; i++) {
        int row = blockIdx.y * 64 + (ty << 2) + i;
        size_t o = (size_t)row * N + col;
        float4 cv;
        cv.x = acc[i][0] + bb.x; cv.y = acc[i][1] + bb.y;
        cv.z = acc[i][2] + bb.z; cv.w = acc[i][3] + bb.w;
        if (EPI == 1) {
            cv.x = gelu_f(cv.x); cv.y = gelu_f(cv.y);
            cv.z = gelu_f(cv.z); cv.w = gelu_f(cv.w);
        } else if (EPI == 2) {
            float4 rv = *(const float4*)&res[o];
            cv.x += rv.x; cv.y += rv.y; cv.z += rv.z; cv.w += rv.w;
        }
        *(float4*)&Cd[o] = cv;
    }
}

/* ---------------- launch ------------------------------------------------ */
extern "C" void kernel_launch(void* const* d_in, const int* in_sizes, int n_in,
                              void* d_out, int out_size) {
    const float* x     = (const float*)d_in[0];
    const float* gt    = (const float*)d_in[1];
    const float* n1g   = (const float*)d_in[2];
    const float* n1b   = (const float*)d_in[3];
    const float* qkvw  = (const float*)d_in[4];
    const float* qkvb  = (const float*)d_in[5];
    const float* btab  = (const float*)d_in[6];
    const float* projw = (const float*)d_in[7];
    const float* projb = (const float*)d_in[8];
    const float* n2g   = (const float*)d_in[9];
    const float* n2b   = (const float*)d_in[10];
    const float* fc1w  = (const float*)d_in[11];
    const float* fc1b  = (const float*)d_in[12];
    const float* fc2w  = (const float*)d_in[13];
    const float* fc2b  = (const float*)d_in[14];
    float* out = (float*)d_out;

    float *xc, *qkv, *ao, *proj, *xres, *ln2b, *hb;
    cudaGetSymbolAddress((void**)&xc,   g_xc);
    cudaGetSymbolAddress((void**)&qkv,  g_qkv);
    cudaGetSymbolAddress((void**)&ao,   g_attnout);
    cudaGetSymbolAddress((void**)&proj, g_proj);
    cudaGetSymbolAddress((void**)&xres, g_xres);
    cudaGetSymbolAddress((void**)&ln2b, g_ln2);
    cudaGetSymbolAddress((void**)&hb,   g_hid);

    cudaFuncSetAttribute(attn_kernel,
                         cudaFuncAttributeMaxDynamicSharedMemorySize,
                         ATT_SMEM_BYTES);

    bias_pre   <<<(NWIN * NWIN + 255) / 256, 256>>>(btab);
    gt_copy    <<<(NW * C_ + 255) / 256, 256>>>(gt);
    ln1_scatter<<<L_ / 8, 256>>>(x, n1g, n1b);

    sgemm<0><<<dim3(3 * C_ / 64, M1 / 64), 256>>>(xc, qkvw, qkvb, nullptr, qkv,
                                                  M1, 3 * C_, C_);

    attn_kernel<<<NW * HEADS, 256, ATT_SMEM_BYTES>>>();

    sgemm<0><<<dim3(C_ / 64, M1 / 64), 256>>>(ao, projw, projb, nullptr, proj,
                                              M1, C_, C_);

    unscatter_res<<<(L_ * C_) / 256, 256>>>(x);
    gt_out_copy  <<<(NW * C_ + 255) / 256, 256>>>(out);
    ln2_kernel   <<<L_ / 8, 256>>>(n2g, n2b);

    sgemm<1><<<dim3(HID / 64, L_ / 64), 256>>>(ln2b, fc1w, fc1b, nullptr, hb,
                                               L_, HID, C_);
    sgemm<2><<<dim3(C_ / 64, L_ / 64), 256>>>(hb, fc2w, fc2b, xres, out,
                                              L_, C_, HID);
}

// round 5
// speedup vs baseline: 1.9824x; 1.9824x over previous
#include <cuda_runtime.h>
#include <math.h>
#include <stdint.h>

#define S_ 7
#define H_ 56
#define W_ 56
#define WS 7
#define C_ 384
#define HEADS 12
#define NW 64
#define NTOK 344
#define NWIN 343
#define L_ (S_*H_*W_)          /* 21952 */
#define M1 (NW*NTOK)           /* 22016 */
#define HID 1536
#define EPS_LN 1e-5f
#define QSCALE 0.17677669529663687f  /* 32^-0.5 */

/* ---------------- scratch (static device globals; no allocation) -------- */
__device__ float g_xc     [(size_t)M1 * C_];        /* tf32-rounded          */
__device__ float g_qkv    [(size_t)M1 * 3 * C_];    /* fp32                  */
__device__ float g_attnout[(size_t)M1 * C_];        /* tf32-rounded          */
__device__ float g_proj   [(size_t)M1 * C_];        /* fp32                  */
__device__ float g_xres   [(size_t)L_ * C_];        /* fp32                  */
__device__ float g_ln2    [(size_t)M1 * C_];        /* tf32-rounded, tail 0  */
__device__ float g_hid    [(size_t)M1 * HID];       /* tf32-rounded          */
__device__ float g_bias   [(size_t)HEADS * NWIN * NWIN];
__device__ float g_wqkv   [(size_t)C_ * 3 * C_];
__device__ float g_wproj  [(size_t)C_ * C_];
__device__ float g_wfc1   [(size_t)C_ * HID];
__device__ float g_wfc2   [(size_t)HID * C_];

/* ---------------- helpers ---------------------------------------------- */
__device__ __forceinline__ float warp_sum(float v) {
    v += __shfl_xor_sync(0xffffffffu, v, 16);
    v += __shfl_xor_sync(0xffffffffu, v, 8);
    v += __shfl_xor_sync(0xffffffffu, v, 4);
    v += __shfl_xor_sync(0xffffffffu, v, 2);
    v += __shfl_xor_sync(0xffffffffu, v, 1);
    return v;
}
__device__ __forceinline__ float warp_max(float v) {
    v = fmaxf(v, __shfl_xor_sync(0xffffffffu, v, 16));
    v = fmaxf(v, __shfl_xor_sync(0xffffffffu, v, 8));
    v = fmaxf(v, __shfl_xor_sync(0xffffffffu, v, 4));
    v = fmaxf(v, __shfl_xor_sync(0xffffffffu, v, 2));
    v = fmaxf(v, __shfl_xor_sync(0xffffffffu, v, 1));
    return v;
}
__device__ __forceinline__ float gelu_f(float v) {
    return 0.5f * v * (1.f + erff(v * 0.7071067811865475f));
}
__device__ __forceinline__ float tf32r(float x) {
    uint32_t u;
    asm("cvt.rna.tf32.f32 %0, %1;" : "=r"(u) : "f"(x));
    return __uint_as_float(u);
}
__device__ __forceinline__ void cpa16(float* s, const float* g) {
    uint32_t sa = (uint32_t)__cvta_generic_to_shared(s);
    asm volatile("cp.async.cg.shared.global [%0], [%1], 16;\n" :: "r"(sa), "l"(g));
}
__device__ __forceinline__ int scatter_row(int l) {
    int s   = l / (H_ * W_);
    int rem = l % (H_ * W_);
    int h   = rem / W_;
    int w   = rem % W_;
    int s2 = (s >= 3) ? s - 3 : s + 4;
    int h2 = (h >= 3) ? h - 3 : h + 53;
    int w2 = (w >= 3) ? w - 3 : w + 53;
    int win = (h2 / WS) * 8 + (w2 / WS);
    int t   = s2 * 49 + (h2 % WS) * 7 + (w2 % WS);
    return win * NTOK + 1 + t;
}

/* ---------------- small kernels ----------------------------------------- */
__global__ void wconv(const float* __restrict__ w, float* __restrict__ o, int n) {
    int i = blockIdx.x * 256 + threadIdx.x;
    if (i < n) o[i] = tf32r(w[i]);
}

__global__ void bias_pre(const float* __restrict__ bt) {
    int idx = blockIdx.x * blockDim.x + threadIdx.x;
    if (idx >= NWIN * NWIN) return;
    int i = idx / NWIN, j = idx % NWIN;
    int si = i / 49, hi = (i / 7) % 7, wi = i % 7;
    int sj = j / 49, hj = (j / 7) % 7, wj = j % 7;
    int r = (si - sj + 6) * 20 + (hi - hj + 6) * 13 + (wi - wj + 6);
#pragma unroll
    for (int h = 0; h < HEADS; h++)
        g_bias[(size_t)h * NWIN * NWIN + idx] = bt[r * HEADS + h];
}

__global__ void gt_copy(const float* __restrict__ gt) {
    int idx = blockIdx.x * blockDim.x + threadIdx.x;
    if (idx >= NW * C_) return;
    int w = idx / C_, c = idx % C_;
    g_xc[((size_t)w * NTOK) * C_ + c] = tf32r(gt[idx]);
}

__global__ void gt_out_copy(float* __restrict__ out) {
    int idx = blockIdx.x * blockDim.x + threadIdx.x;
    if (idx >= NW * C_) return;
    int w = idx / C_, c = idx % C_;
    out[(size_t)L_ * C_ + idx] = g_proj[((size_t)w * NTOK) * C_ + c];
}

__global__ void ln1_scatter(const float* __restrict__ x,
                            const float* __restrict__ g,
                            const float* __restrict__ b) {
    int gw   = (blockIdx.x * blockDim.x + threadIdx.x) >> 5;
    int lane = threadIdx.x & 31;
    if (gw >= L_) return;
    const float* xi = x + (size_t)gw * C_;
    float v[12];
    float sum = 0.f;
#pragma unroll
    for (int m = 0; m < 12; m++) { v[m] = xi[lane + m * 32]; sum += v[m]; }
    sum = warp_sum(sum);
    float mu = sum * (1.f / 384.f);
    float vs = 0.f;
#pragma unroll
    for (int m = 0; m < 12; m++) { float d = v[m] - mu; vs += d * d; }
    vs = warp_sum(vs);
    float rstd = rsqrtf(vs * (1.f / 384.f) + EPS_LN);
    float* o = g_xc + (size_t)scatter_row(gw) * C_;
#pragma unroll
    for (int m = 0; m < 12; m++) {
        int c = lane + m * 32;
        o[c] = tf32r((v[m] - mu) * rstd * g[c] + b[c]);
    }
}

__global__ void ln2_kernel(const float* __restrict__ g,
                           const float* __restrict__ b) {
    int gw   = (blockIdx.x * blockDim.x + threadIdx.x) >> 5;
    int lane = threadIdx.x & 31;
    if (gw >= L_) return;
    const float* xi = g_xres + (size_t)gw * C_;
    float v[12];
    float sum = 0.f;
#pragma unroll
    for (int m = 0; m < 12; m++) { v[m] = xi[lane + m * 32]; sum += v[m]; }
    sum = warp_sum(sum);
    float mu = sum * (1.f / 384.f);
    float vs = 0.f;
#pragma unroll
    for (int m = 0; m < 12; m++) { float d = v[m] - mu; vs += d * d; }
    vs = warp_sum(vs);
    float rstd = rsqrtf(vs * (1.f / 384.f) + EPS_LN);
    float* o = g_ln2 + (size_t)gw * C_;
#pragma unroll
    for (int m = 0; m < 12; m++) {
        int c = lane + m * 32;
        o[c] = tf32r((v[m] - mu) * rstd * g[c] + b[c]);
    }
}

__global__ void unscatter_res(const float* __restrict__ x) {
    int idx = blockIdx.x * blockDim.x + threadIdx.x;
    if (idx >= L_ * C_) return;
    int l = idx / C_, c = idx % C_;
    g_xres[idx] = x[idx] + g_proj[(size_t)scatter_row(l) * C_ + c];
}

/* ---------------- fused attention: one block per (window, head) --------- */
#define KSTRIDE 36
#define ATT_SMEM_BYTES ((NTOK*KSTRIDE*2 + 8*NTOK + 8*32) * 4 + NTOK * 4)

__global__ __launch_bounds__(256) void attn_kernel() {
    extern __shared__ float sm[];
    float* Ks = sm;                       /* 344*36 */
    float* Vs = Ks + NTOK * KSTRIDE;      /* 344*36 */
    float* Ps = Vs + NTOK * KSTRIDE;      /* 8*344  */
    float* Qs = Ps + 8 * NTOK;            /* 8*32   */
    int*  lab = (int*)(Qs + 8 * 32);      /* 344    */

    int tid = threadIdx.x, wid = tid >> 5, lane = tid & 31;
    int win = blockIdx.x / HEADS, head = blockIdx.x % HEADS;
    const float* base = g_qkv + (size_t)win * NTOK * (3 * C_) + head * 32;

    for (int idx = tid; idx < NTOK * 32; idx += 256) {
        int j = idx >> 5, dd = idx & 31;
        size_t ro = (size_t)j * (3 * C_);
        Ks[j * KSTRIDE + dd] = base[ro + C_ + dd];
        Vs[j * KSTRIDE + dd] = base[ro + 2 * C_ + dd];
    }
    int wh = win >> 3, ww = win & 7;
    for (int t = tid; t < NTOK; t += 256) {
        int lv = -1;
        if (t > 0) {
            int t0 = t - 1;
            int ts = t0 / 49, th = (t0 / 7) % 7, tw = t0 % 7;
            int hh = wh * 7 + th, wc = ww * 7 + tw;
            int ia = (ts < 4) ? 1 : 2;
            int ib = (hh < 49) ? 0 : ((hh < 53) ? 1 : 2);
            int ic = (wc < 49) ? 0 : ((wc < 53) ? 1 : 2);
            lv = ia * 9 + ib * 3 + ic;
        }
        lab[t] = lv;
    }
    __syncthreads();

    const float* bh = g_bias + (size_t)head * NWIN * NWIN;
    for (int r = wid; r < NTOK; r += 8) {
        Qs[wid * 32 + lane] = base[(size_t)r * (3 * C_) + lane] * QSCALE;
        __syncwarp();
        int lr = lab[r];
        const float4* q4 = (const float4*)(Qs + wid * 32);
        float s[11];
#pragma unroll
        for (int m = 0; m < 11; m++) {
            int j = lane + (m << 5);
            float acc;
            if (j < NTOK) {
                const float4* k4 = (const float4*)(Ks + j * KSTRIDE);
                acc = 0.f;
#pragma unroll
                for (int q = 0; q < 8; q++) {
                    float4 kk = k4[q], qq = q4[q];
                    acc += kk.x * qq.x; acc += kk.y * qq.y;
                    acc += kk.z * qq.z; acc += kk.w * qq.w;
                }
                if (r > 0 && j > 0) {
                    acc += bh[(r - 1) * NWIN + (j - 1)];
                    if (lr != lab[j]) acc -= 100.f;
                }
            } else {
                acc = -1e30f;
            }
            s[m] = acc;
        }
        float mx = s[0];
#pragma unroll
        for (int m = 1; m < 11; m++) mx = fmaxf(mx, s[m]);
        mx = warp_max(mx);
        float sum = 0.f;
#pragma unroll
        for (int m = 0; m < 11; m++) { float e = __expf(s[m] - mx); s[m] = e; sum += e; }
        sum = warp_sum(sum);
        float inv = 1.f / sum;
#pragma unroll
        for (int m = 0; m < 11; m++) {
            int j = lane + (m << 5);
            if (j < NTOK) Ps[wid * NTOK + j] = s[m] * inv;
        }
        __syncwarp();
        float o = 0.f;
        const float4* p4 = (const float4*)(Ps + wid * NTOK);
#pragma unroll 2
        for (int jq = 0; jq < NTOK / 4; jq++) {
            float4 p = p4[jq];
            int j = jq << 2;
            o += p.x * Vs[(j + 0) * KSTRIDE + lane];
            o += p.y * Vs[(j + 1) * KSTRIDE + lane];
            o += p.z * Vs[(j + 2) * KSTRIDE + lane];
            o += p.w * Vs[(j + 3) * KSTRIDE + lane];
        }
        g_attnout[((size_t)win * NTOK + r) * C_ + head * 32 + lane] = tf32r(o);
        __syncwarp();
    }
}

/* ---------------- TF32 tensor-core GEMM --------------------------------- */
/* C = A[Mpad x K] @ B[K x N] + bias, tile 128x128x32, mma.m16n8k8.tf32.
   A smem [128][36] (pad), B smem [32][136] (pad), cp.async double buffer.
   EPI: 0 none, 1 gelu, 2 +res.  CVT: tf32-round before store.            */
#define ASTRIDE 36
#define BSTRIDE 136
#define ABUF 4608            /* 128*36 floats  */
#define BBUF 4352            /* 32*136 floats  */
#define GEMM_SMEM_BYTES ((2*ABUF + 2*BBUF) * 4)   /* 71680 */

template<int EPI, int CVT>
__global__ __launch_bounds__(256, 2) void gemm_tc(const float* __restrict__ A,
                                                  const float* __restrict__ B,
                                                  const float* __restrict__ bias,
                                                  const float* __restrict__ res,
                                                  float* __restrict__ Cd,
                                                  int Mstore, int N, int K) {
    extern __shared__ float sm[];
    const int tid = threadIdx.x, lane = tid & 31, wid = tid >> 5;
    const int bm = blockIdx.y * 128, bn = blockIdx.x * 128;
    const int wm = (wid & 1) * 64, wn = (wid >> 1) * 32;

    float c[4][4][4];
#pragma unroll
    for (int i = 0; i < 4; i++)
#pragma unroll
        for (int j = 0; j < 4; j++)
#pragma unroll
            for (int k = 0; k < 4; k++) c[i][j][k] = 0.f;

    const int NK = K >> 5;

    /* cp.async load of one 128x32 A tile + 32x128 B tile */
    auto issue = [&](int kt, int p) {
        float* As = sm + p * ABUF;
        float* Bs = sm + 2 * ABUF + p * BBUF;
        const float* Ag = A + (size_t)bm * K + kt * 32;
        const float* Bg = B + (size_t)(kt * 32) * N + bn;
#pragma unroll
        for (int i = 0; i < 4; i++) {
            int idx = tid + i * 256;
            int r = idx >> 3, c4 = (idx & 7) * 4;
            cpa16(As + r * ASTRIDE + c4, Ag + (size_t)r * K + c4);
        }
#pragma unroll
        for (int i = 0; i < 4; i++) {
            int idx = tid + i * 256;
            int r = idx >> 5, cc = (idx & 31) * 4;
            cpa16(Bs + r * BSTRIDE + cc, Bg + (size_t)r * N + cc);
        }
    };

    issue(0, 0);
    asm volatile("cp.async.commit_group;\n");

    int p = 0;
    for (int kt = 0; kt < NK; kt++) {
        if (kt + 1 < NK) {
            issue(kt + 1, p ^ 1);
            asm volatile("cp.async.commit_group;\n");
            asm volatile("cp.async.wait_group 1;\n");
        } else {
            asm volatile("cp.async.wait_group 0;\n");
        }
        __syncthreads();

        const float* As = sm + p * ABUF;
        const float* Bs = sm + 2 * ABUF + p * BBUF;
#pragma unroll
        for (int ks = 0; ks < 4; ks++) {
            uint32_t a[4][4], b[4][2];
            int arow = wm + (lane >> 2);
            int acol = ks * 8 + (lane & 3);
#pragma unroll
            for (int mt = 0; mt < 4; mt++) {
                int r = arow + mt * 16;
                a[mt][0] = __float_as_uint(As[(r    ) * ASTRIDE + acol    ]);
                a[mt][1] = __float_as_uint(As[(r + 8) * ASTRIDE + acol    ]);
                a[mt][2] = __float_as_uint(As[(r    ) * ASTRIDE + acol + 4]);
                a[mt][3] = __float_as_uint(As[(r + 8) * ASTRIDE + acol + 4]);
            }
            int brow = ks * 8 + (lane & 3);
            int bcol = wn + (lane >> 2);
#pragma unroll
            for (int nt = 0; nt < 4; nt++) {
                b[nt][0] = __float_as_uint(Bs[(brow    ) * BSTRIDE + bcol + nt * 8]);
                b[nt][1] = __float_as_uint(Bs[(brow + 4) * BSTRIDE + bcol + nt * 8]);
            }
#pragma unroll
            for (int mt = 0; mt < 4; mt++)
#pragma unroll
                for (int nt = 0; nt < 4; nt++) {
                    asm volatile(
                        "mma.sync.aligned.m16n8k8.row.col.f32.tf32.tf32.f32 "
                        "{%0,%1,%2,%3}, {%4,%5,%6,%7}, {%8,%9}, {%0,%1,%2,%3};\n"
                        : "+f"(c[mt][nt][0]), "+f"(c[mt][nt][1]),
                          "+f"(c[mt][nt][2]), "+f"(c[mt][nt][3])
                        : "r"(a[mt][0]), "r"(a[mt][1]), "r"(a[mt][2]), "r"(a[mt][3]),
                          "r"(b[nt][0]), "r"(b[nt][1]));
                }
        }
        __syncthreads();
        p ^= 1;
    }

    /* epilogue */
#pragma unroll
    for (int nt = 0; nt < 4; nt++) {
        int col = bn + wn + nt * 8 + 2 * (lane & 3);
        float2 bb = *(const float2*)&bias[col];
#pragma unroll
        for (int mt = 0; mt < 4; mt++) {
            int row0 = bm + wm + mt * 16 + (lane >> 2);
#pragma unroll
            for (int h = 0; h < 2; h++) {
                int row = row0 + h * 8;
                if (row < Mstore) {
                    float2 v;
                    v.x = c[mt][nt][2 * h]     + bb.x;
                    v.y = c[mt][nt][2 * h + 1] + bb.y;
                    if (EPI == 1) { v.x = gelu_f(v.x); v.y = gelu_f(v.y); }
                    size_t o = (size_t)row * N + col;
                    if (EPI == 2) {
                        float2 rv = *(const float2*)&res[o];
                        v.x += rv.x; v.y += rv.y;
                    }
                    if (CVT) { v.x = tf32r(v.x); v.y = tf32r(v.y); }
                    *(float2*)&Cd[o] = v;
                }
            }
        }
    }
}

/* ---------------- launch ------------------------------------------------ */
extern "C" void kernel_launch(void* const* d_in, const int* in_sizes, int n_in,
                              void* d_out, int out_size) {
    const float* x     = (const float*)d_in[0];
    const float* gt    = (const float*)d_in[1];
    const float* n1g   = (const float*)d_in[2];
    const float* n1b   = (const float*)d_in[3];
    const float* qkvw  = (const float*)d_in[4];
    const float* qkvb  = (const float*)d_in[5];
    const float* btab  = (const float*)d_in[6];
    const float* projw = (const float*)d_in[7];
    const float* projb = (const float*)d_in[8];
    const float* n2g   = (const float*)d_in[9];
    const float* n2b   = (const float*)d_in[10];
    const float* fc1w  = (const float*)d_in[11];
    const float* fc1b  = (const float*)d_in[12];
    const float* fc2w  = (const float*)d_in[13];
    const float* fc2b  = (const float*)d_in[14];
    float* out = (float*)d_out;

    float *xc, *qkv, *ao, *proj, *xres, *ln2b, *hb;
    float *wq, *wp, *w1, *w2;
    cudaGetSymbolAddress((void**)&xc,   g_xc);
    cudaGetSymbolAddress((void**)&qkv,  g_qkv);
    cudaGetSymbolAddress((void**)&ao,   g_attnout);
    cudaGetSymbolAddress((void**)&proj, g_proj);
    cudaGetSymbolAddress((void**)&xres, g_xres);
    cudaGetSymbolAddress((void**)&ln2b, g_ln2);
    cudaGetSymbolAddress((void**)&hb,   g_hid);
    cudaGetSymbolAddress((void**)&wq,   g_wqkv);
    cudaGetSymbolAddress((void**)&wp,   g_wproj);
    cudaGetSymbolAddress((void**)&w1,   g_wfc1);
    cudaGetSymbolAddress((void**)&w2,   g_wfc2);

    cudaFuncSetAttribute(attn_kernel,
                         cudaFuncAttributeMaxDynamicSharedMemorySize,
                         ATT_SMEM_BYTES);
    cudaFuncSetAttribute(gemm_tc<0, 0>,
                         cudaFuncAttributeMaxDynamicSharedMemorySize,
                         GEMM_SMEM_BYTES);
    cudaFuncSetAttribute(gemm_tc<1, 1>,
                         cudaFuncAttributeMaxDynamicSharedMemorySize,
                         GEMM_SMEM_BYTES);
    cudaFuncSetAttribute(gemm_tc<2, 0>,
                         cudaFuncAttributeMaxDynamicSharedMemorySize,
                         GEMM_SMEM_BYTES);

    /* weight tf32 pre-rounding */
    wconv<<<(C_ * 3 * C_ + 255) / 256, 256>>>(qkvw, wq, C_ * 3 * C_);
    wconv<<<(C_ * C_ + 255) / 256, 256>>>(projw, wp, C_ * C_);
    wconv<<<(C_ * HID + 255) / 256, 256>>>(fc1w, w1, C_ * HID);
    wconv<<<(HID * C_ + 255) / 256, 256>>>(fc2w, w2, HID * C_);

    bias_pre   <<<(NWIN * NWIN + 255) / 256, 256>>>(btab);
    gt_copy    <<<(NW * C_ + 255) / 256, 256>>>(gt);
    ln1_scatter<<<L_ / 8, 256>>>(x, n1g, n1b);

    gemm_tc<0, 0><<<dim3((3 * C_) / 128, M1 / 128), 256, GEMM_SMEM_BYTES>>>(
        xc, wq, qkvb, nullptr, qkv, M1, 3 * C_, C_);

    attn_kernel<<<NW * HEADS, 256, ATT_SMEM_BYTES>>>();

    gemm_tc<0, 0><<<dim3(C_ / 128, M1 / 128), 256, GEMM_SMEM_BYTES>>>(
        ao, wp, projb, nullptr, proj, M1, C_, C_);

    unscatter_res<<<(L_ * C_) / 256, 256>>>(x);
    gt_out_copy  <<<(NW * C_ + 255) / 256, 256>>>(out);
    ln2_kernel   <<<L_ / 8, 256>>>(n2g, n2b);

    gemm_tc<1, 1><<<dim3(HID / 128, M1 / 128), 256, GEMM_SMEM_BYTES>>>(
        ln2b, w1, fc1b, nullptr, hb, M1, HID, C_);

    gemm_tc<2, 0><<<dim3(C_ / 128, M1 / 128), 256, GEMM_SMEM_BYTES>>>(
        hb, w2, fc2b, xres, out, L_, C_, HID);
}

// round 6
// speedup vs baseline: 2.8284x; 1.4267x over previous
#include <cuda_runtime.h>
#include <math.h>
#include <stdint.h>

#define S_ 7
#define H_ 56
#define W_ 56
#define WS 7
#define C_ 384
#define HEADS 12
#define NW 64
#define NTOK 344
#define NWIN 343
#define L_ (S_*H_*W_)          /* 21952 */
#define M1 (NW*NTOK)           /* 22016 */
#define HID 1536
#define EPS_LN 1e-5f
#define QSCALE 0.17677669529663687f  /* 32^-0.5 */

/* ---------------- scratch (static device globals; no allocation) -------- */
__device__ float g_xc     [(size_t)M1 * C_];
__device__ float g_qkv    [(size_t)M1 * 3 * C_];
__device__ float g_attnout[(size_t)M1 * C_];
__device__ float g_proj   [(size_t)M1 * C_];
__device__ float g_xres   [(size_t)L_ * C_];
__device__ float g_ln2    [(size_t)M1 * C_];
__device__ float g_hid    [(size_t)M1 * HID];
__device__ float g_bias   [(size_t)HEADS * NWIN * NWIN];
__device__ float g_wqkv   [(size_t)C_ * 3 * C_];
__device__ float g_wproj  [(size_t)C_ * C_];
__device__ float g_wfc1   [(size_t)C_ * HID];
__device__ float g_wfc2   [(size_t)HID * C_];

/* ---------------- helpers ---------------------------------------------- */
__device__ __forceinline__ float warp_sum(float v) {
    v += __shfl_xor_sync(0xffffffffu, v, 16);
    v += __shfl_xor_sync(0xffffffffu, v, 8);
    v += __shfl_xor_sync(0xffffffffu, v, 4);
    v += __shfl_xor_sync(0xffffffffu, v, 2);
    v += __shfl_xor_sync(0xffffffffu, v, 1);
    return v;
}
__device__ __forceinline__ float warp_max(float v) {
    v = fmaxf(v, __shfl_xor_sync(0xffffffffu, v, 16));
    v = fmaxf(v, __shfl_xor_sync(0xffffffffu, v, 8));
    v = fmaxf(v, __shfl_xor_sync(0xffffffffu, v, 4));
    v = fmaxf(v, __shfl_xor_sync(0xffffffffu, v, 2));
    v = fmaxf(v, __shfl_xor_sync(0xffffffffu, v, 1));
    return v;
}
__device__ __forceinline__ float gelu_f(float v) {
    return 0.5f * v * (1.f + erff(v * 0.7071067811865475f));
}
__device__ __forceinline__ float tf32r(float x) {
    uint32_t u;
    asm("cvt.rna.tf32.f32 %0, %1;" : "=r"(u) : "f"(x));
    return __uint_as_float(u);
}
__device__ __forceinline__ void cpa16(float* s, const float* g) {
    uint32_t sa = (uint32_t)__cvta_generic_to_shared(s);
    asm volatile("cp.async.cg.shared.global [%0], [%1], 16;\n" :: "r"(sa), "l"(g));
}
#define MMA_TF32(c4, a4, b2)                                                   \
    asm volatile(                                                              \
        "mma.sync.aligned.m16n8k8.row.col.f32.tf32.tf32.f32 "                  \
        "{%0,%1,%2,%3}, {%4,%5,%6,%7}, {%8,%9}, {%0,%1,%2,%3};\n"              \
        : "+f"((c4)[0]), "+f"((c4)[1]), "+f"((c4)[2]), "+f"((c4)[3])           \
        : "r"((a4)[0]), "r"((a4)[1]), "r"((a4)[2]), "r"((a4)[3]),              \
          "r"((b2)[0]), "r"((b2)[1]))

__device__ __forceinline__ int scatter_row(int l) {
    int s   = l / (H_ * W_);
    int rem = l % (H_ * W_);
    int h   = rem / W_;
    int w   = rem % W_;
    int s2 = (s >= 3) ? s - 3 : s + 4;
    int h2 = (h >= 3) ? h - 3 : h + 53;
    int w2 = (w >= 3) ? w - 3 : w + 53;
    int win = (h2 / WS) * 8 + (w2 / WS);
    int t   = s2 * 49 + (h2 % WS) * 7 + (w2 % WS);
    return win * NTOK + 1 + t;
}

/* ---------------- small kernels ----------------------------------------- */
__global__ void wconv(const float* __restrict__ w, float* __restrict__ o, int n) {
    int i = blockIdx.x * 256 + threadIdx.x;
    if (i < n) o[i] = tf32r(w[i]);
}

__global__ void bias_pre(const float* __restrict__ bt) {
    int idx = blockIdx.x * blockDim.x + threadIdx.x;
    if (idx >= NWIN * NWIN) return;
    int i = idx / NWIN, j = idx % NWIN;
    int si = i / 49, hi = (i / 7) % 7, wi = i % 7;
    int sj = j / 49, hj = (j / 7) % 7, wj = j % 7;
    int r = (si - sj + 6) * 20 + (hi - hj + 6) * 13 + (wi - wj + 6);
#pragma unroll
    for (int h = 0; h < HEADS; h++)
        g_bias[(size_t)h * NWIN * NWIN + idx] = bt[r * HEADS + h];
}

__global__ void gt_copy(const float* __restrict__ gt) {
    int idx = blockIdx.x * blockDim.x + threadIdx.x;
    if (idx >= NW * C_) return;
    int w = idx / C_, c = idx % C_;
    g_xc[((size_t)w * NTOK) * C_ + c] = tf32r(gt[idx]);
}

__global__ void gt_out_copy(float* __restrict__ out) {
    int idx = blockIdx.x * blockDim.x + threadIdx.x;
    if (idx >= NW * C_) return;
    int w = idx / C_, c = idx % C_;
    out[(size_t)L_ * C_ + idx] = g_proj[((size_t)w * NTOK) * C_ + c];
}

__global__ void ln1_scatter(const float* __restrict__ x,
                            const float* __restrict__ g,
                            const float* __restrict__ b) {
    int gw   = (blockIdx.x * blockDim.x + threadIdx.x) >> 5;
    int lane = threadIdx.x & 31;
    if (gw >= L_) return;
    const float* xi = x + (size_t)gw * C_;
    float v[12];
    float sum = 0.f;
#pragma unroll
    for (int m = 0; m < 12; m++) { v[m] = xi[lane + m * 32]; sum += v[m]; }
    sum = warp_sum(sum);
    float mu = sum * (1.f / 384.f);
    float vs = 0.f;
#pragma unroll
    for (int m = 0; m < 12; m++) { float d = v[m] - mu; vs += d * d; }
    vs = warp_sum(vs);
    float rstd = rsqrtf(vs * (1.f / 384.f) + EPS_LN);
    float* o = g_xc + (size_t)scatter_row(gw) * C_;
#pragma unroll
    for (int m = 0; m < 12; m++) {
        int c = lane + m * 32;
        o[c] = tf32r((v[m] - mu) * rstd * g[c] + b[c]);
    }
}

__global__ void ln2_kernel(const float* __restrict__ g,
                           const float* __restrict__ b) {
    int gw   = (blockIdx.x * blockDim.x + threadIdx.x) >> 5;
    int lane = threadIdx.x & 31;
    if (gw >= L_) return;
    const float* xi = g_xres + (size_t)gw * C_;
    float v[12];
    float sum = 0.f;
#pragma unroll
    for (int m = 0; m < 12; m++) { v[m] = xi[lane + m * 32]; sum += v[m]; }
    sum = warp_sum(sum);
    float mu = sum * (1.f / 384.f);
    float vs = 0.f;
#pragma unroll
    for (int m = 0; m < 12; m++) { float d = v[m] - mu; vs += d * d; }
    vs = warp_sum(vs);
    float rstd = rsqrtf(vs * (1.f / 384.f) + EPS_LN);
    float* o = g_ln2 + (size_t)gw * C_;
#pragma unroll
    for (int m = 0; m < 12; m++) {
        int c = lane + m * 32;
        o[c] = tf32r((v[m] - mu) * rstd * g[c] + b[c]);
    }
}

__global__ void unscatter_res(const float* __restrict__ x) {
    int idx = blockIdx.x * blockDim.x + threadIdx.x;
    if (idx >= L_ * C_) return;
    int l = idx / C_, c = idx % C_;
    g_xres[idx] = x[idx] + g_proj[(size_t)scatter_row(l) * C_ + c];
}

/* ---------------- attention via tf32 mma -------------------------------- */
/* One block per (window, head). smem:
     Ks [32][KSTR]   K transposed (d-major), tf32, cols 344..351 zero
     Vs [NTOK][VSTR] V, tf32
     Ss [64][SSTR]   score tile / P tile
     Qs [64][QSTR]   Q tile, scaled, tf32
   Strides chosen for conflict-free mma fragment access:
     KSTR%32==8 (b-frag: (lane&3)*8+(lane>>2) distinct)
     VSTR%32==8 (b-frag: same)
     SSTR%32==4 (a-frag: (lane>>2)*4+(lane&3) distinct)
     QSTR%32==4 (a-frag: same)                                              */
#define KSTR 360
#define VSTR 40
#define SSTR 356
#define QSTR 36
#define NPAD 352
#define ATT2_SMEM ((32*KSTR + NTOK*VSTR + 64*SSTR + 64*QSTR) * 4 + NTOK * 4)

__global__ __launch_bounds__(256, 1) void attn_mma() {
    extern __shared__ float sm[];
    float* Ks = sm;
    float* Vs = Ks + 32 * KSTR;
    float* Ss = Vs + NTOK * VSTR;
    float* Qs = Ss + 64 * SSTR;
    int*  lab = (int*)(Qs + 64 * QSTR);

    int tid = threadIdx.x, lane = tid & 31, wid = tid >> 5;
    int win = blockIdx.x / HEADS, head = blockIdx.x % HEADS;
    const float* base = g_qkv + (size_t)win * NTOK * (3 * C_) + head * 32;

    /* K transposed (+zero pad cols), V */
    for (int idx = tid; idx < 32 * NPAD; idx += 256) {
        int n = idx >> 5, d = idx & 31;
        float v = (n < NTOK) ? base[(size_t)n * (3 * C_) + C_ + d] : 0.f;
        Ks[d * KSTR + n] = tf32r(v);
    }
    for (int idx = tid; idx < NTOK * 32; idx += 256) {
        int j = idx >> 5, d = idx & 31;
        Vs[j * VSTR + d] = tf32r(base[(size_t)j * (3 * C_) + 2 * C_ + d]);
    }
    int wh = win >> 3, ww = win & 7;
    for (int t = tid; t < NTOK; t += 256) {
        int lv = -1;
        if (t > 0) {
            int t0 = t - 1;
            int ts = t0 / 49, th = (t0 / 7) % 7, tw = t0 % 7;
            int hh = wh * 7 + th, wc = ww * 7 + tw;
            int ia = (ts < 4) ? 1 : 2;
            int ib = (hh < 49) ? 0 : ((hh < 53) ? 1 : 2);
            int ic = (wc < 49) ? 0 : ((wc < 53) ? 1 : 2);
            lv = ia * 9 + ib * 3 + ic;
        }
        lab[t] = lv;
    }
    __syncthreads();

    const float* bh = g_bias + (size_t)head * NWIN * NWIN;
    const int wm  = (wid & 1) * 32;     /* warp M offset (rows in tile)  */
    const int wn  = (wid >> 1) * 88;    /* warp N offset for QK (cols)   */
    const int wnO = (wid >> 1) * 8;     /* warp N offset for PV (dims)   */

    for (int qt = 0; qt < 6; qt++) {
        int qbase = qt * 64;
        /* Q tile (scaled, guarded, tf32) */
        for (int i = tid; i < 64 * 32; i += 256) {
            int m = i >> 5, d = i & 31;
            int r = qbase + m;
            float v = (r < NTOK) ? base[(size_t)r * (3 * C_) + d] * QSCALE : 0.f;
            Qs[m * QSTR + d] = tf32r(v);
        }
        __syncthreads();

        /* ---- S = Q K^T ---- */
        float c[2][11][4];
#pragma unroll
        for (int mt = 0; mt < 2; mt++)
#pragma unroll
            for (int nt = 0; nt < 11; nt++)
#pragma unroll
                for (int q = 0; q < 4; q++) c[mt][nt][q] = 0.f;

#pragma unroll
        for (int ks = 0; ks < 4; ks++) {
            uint32_t a[2][4];
            int acol = ks * 8 + (lane & 3);
#pragma unroll
            for (int mt = 0; mt < 2; mt++) {
                int r = wm + mt * 16 + (lane >> 2);
                a[mt][0] = __float_as_uint(Qs[(r    ) * QSTR + acol    ]);
                a[mt][1] = __float_as_uint(Qs[(r + 8) * QSTR + acol    ]);
                a[mt][2] = __float_as_uint(Qs[(r    ) * QSTR + acol + 4]);
                a[mt][3] = __float_as_uint(Qs[(r + 8) * QSTR + acol + 4]);
            }
#pragma unroll
            for (int nt = 0; nt < 11; nt++) {
                uint32_t b[2];
                int bc = wn + nt * 8 + (lane >> 2);
                b[0] = __float_as_uint(Ks[(ks * 8 + (lane & 3)    ) * KSTR + bc]);
                b[1] = __float_as_uint(Ks[(ks * 8 + (lane & 3) + 4) * KSTR + bc]);
                MMA_TF32(c[0][nt], a[0], b);
                MMA_TF32(c[1][nt], a[1], b);
            }
        }

        /* ---- store S + bias + mask ---- */
#pragma unroll
        for (int mt = 0; mt < 2; mt++) {
            int r0 = wm + mt * 16 + (lane >> 2);
#pragma unroll
            for (int nt = 0; nt < 11; nt++) {
                int j0 = wn + nt * 8 + 2 * (lane & 3);
#pragma unroll
                for (int h = 0; h < 2; h++) {
                    int rr = r0 + h * 8;
                    int rg = qbase + rr;
                    float v0 = c[mt][nt][2 * h];
                    float v1 = c[mt][nt][2 * h + 1];
                    if (rg < NTOK && rg > 0) {
                        int lr = lab[rg];
                        if (j0 < NTOK && j0 > 0) {
                            v0 += bh[(rg - 1) * NWIN + (j0 - 1)];
                            if (lr != lab[j0]) v0 -= 100.f;
                        }
                        int j1 = j0 + 1;
                        if (j1 < NTOK) {
                            v1 += bh[(rg - 1) * NWIN + (j1 - 1)];
                            if (lr != lab[j1]) v1 -= 100.f;
                        }
                    }
                    if (j0 >= NTOK)     v0 = -1e30f;
                    if (j0 + 1 >= NTOK) v1 = -1e30f;
                    Ss[rr * SSTR + j0]     = v0;
                    Ss[rr * SSTR + j0 + 1] = v1;
                }
            }
        }
        __syncthreads();

        /* ---- softmax (8 rows per warp), write P tf32 ---- */
#pragma unroll
        for (int i = 0; i < 8; i++) {
            int rr = wid * 8 + i;
            float s[11];
            float mx = -1e30f;
#pragma unroll
            for (int m = 0; m < 11; m++) {
                s[m] = Ss[rr * SSTR + lane + m * 32];
                mx = fmaxf(mx, s[m]);
            }
            mx = warp_max(mx);
            float sum = 0.f;
#pragma unroll
            for (int m = 0; m < 11; m++) {
                float e = __expf(s[m] - mx);
                s[m] = e; sum += e;
            }
            sum = warp_sum(sum);
            float inv = 1.f / sum;
#pragma unroll
            for (int m = 0; m < 11; m++)
                Ss[rr * SSTR + lane + m * 32] = tf32r(s[m] * inv);
        }
        __syncthreads();

        /* ---- O = P V ---- */
        float o[2][4] = {};
#pragma unroll 4
        for (int kt = 0; kt < 43; kt++) {
            uint32_t b[2];
            int kr = kt * 8 + (lane & 3);
            int bc = wnO + (lane >> 2);
            b[0] = __float_as_uint(Vs[(kr    ) * VSTR + bc]);
            b[1] = __float_as_uint(Vs[(kr + 4) * VSTR + bc]);
#pragma unroll
            for (int mt = 0; mt < 2; mt++) {
                uint32_t a[4];
                int r  = wm + mt * 16 + (lane >> 2);
                int ac = kt * 8 + (lane & 3);
                a[0] = __float_as_uint(Ss[(r    ) * SSTR + ac    ]);
                a[1] = __float_as_uint(Ss[(r + 8) * SSTR + ac    ]);
                a[2] = __float_as_uint(Ss[(r    ) * SSTR + ac + 4]);
                a[3] = __float_as_uint(Ss[(r + 8) * SSTR + ac + 4]);
                MMA_TF32(o[mt], a, b);
            }
        }
#pragma unroll
        for (int mt = 0; mt < 2; mt++)
#pragma unroll
            for (int h = 0; h < 2; h++) {
                int rr = qbase + wm + mt * 16 + (lane >> 2) + h * 8;
                if (rr < NTOK) {
                    float2 v;
                    v.x = tf32r(o[mt][2 * h]);
                    v.y = tf32r(o[mt][2 * h + 1]);
                    *(float2*)&g_attnout[((size_t)win * NTOK + rr) * C_ +
                                         head * 32 + wnO + 2 * (lane & 3)] = v;
                }
            }
        __syncthreads();
    }
}

/* ---------------- TF32 tensor-core GEMM --------------------------------- */
#define ASTRIDE 36
#define BSTRIDE 136
#define ABUF 4608
#define BBUF 4352
#define GEMM_SMEM_BYTES ((2*ABUF + 2*BBUF) * 4)   /* 71680 */

template<int EPI, int CVT>
__global__ __launch_bounds__(256, 2) void gemm_tc(const float* __restrict__ A,
                                                  const float* __restrict__ B,
                                                  const float* __restrict__ bias,
                                                  const float* __restrict__ res,
                                                  float* __restrict__ Cd,
                                                  int Mstore, int N, int K) {
    extern __shared__ float sm[];
    const int tid = threadIdx.x, lane = tid & 31, wid = tid >> 5;
    const int bm = blockIdx.y * 128, bn = blockIdx.x * 128;
    const int wm = (wid & 1) * 64, wn = (wid >> 1) * 32;

    float c[4][4][4];
#pragma unroll
    for (int i = 0; i < 4; i++)
#pragma unroll
        for (int j = 0; j < 4; j++)
#pragma unroll
            for (int k = 0; k < 4; k++) c[i][j][k] = 0.f;

    const int NK = K >> 5;

    auto issue = [&](int kt, int p) {
        float* As = sm + p * ABUF;
        float* Bs = sm + 2 * ABUF + p * BBUF;
        const float* Ag = A + (size_t)bm * K + kt * 32;
        const float* Bg = B + (size_t)(kt * 32) * N + bn;
#pragma unroll
        for (int i = 0; i < 4; i++) {
            int idx = tid + i * 256;
            int r = idx >> 3, c4 = (idx & 7) * 4;
            cpa16(As + r * ASTRIDE + c4, Ag + (size_t)r * K + c4);
        }
#pragma unroll
        for (int i = 0; i < 4; i++) {
            int idx = tid + i * 256;
            int r = idx >> 5, cc = (idx & 31) * 4;
            cpa16(Bs + r * BSTRIDE + cc, Bg + (size_t)r * N + cc);
        }
    };

    issue(0, 0);
    asm volatile("cp.async.commit_group;\n");

    int p = 0;
    for (int kt = 0; kt < NK; kt++) {
        if (kt + 1 < NK) {
            issue(kt + 1, p ^ 1);
            asm volatile("cp.async.commit_group;\n");
            asm volatile("cp.async.wait_group 1;\n");
        } else {
            asm volatile("cp.async.wait_group 0;\n");
        }
        __syncthreads();

        const float* As = sm + p * ABUF;
        const float* Bs = sm + 2 * ABUF + p * BBUF;
#pragma unroll
        for (int ks = 0; ks < 4; ks++) {
            uint32_t a[4][4], b[4][2];
            int arow = wm + (lane >> 2);
            int acol = ks * 8 + (lane & 3);
#pragma unroll
            for (int mt = 0; mt < 4; mt++) {
                int r = arow + mt * 16;
                a[mt][0] = __float_as_uint(As[(r    ) * ASTRIDE + acol    ]);
                a[mt][1] = __float_as_uint(As[(r + 8) * ASTRIDE + acol    ]);
                a[mt][2] = __float_as_uint(As[(r    ) * ASTRIDE + acol + 4]);
                a[mt][3] = __float_as_uint(As[(r + 8) * ASTRIDE + acol + 4]);
            }
            int brow = ks * 8 + (lane & 3);
            int bcol = wn + (lane >> 2);
#pragma unroll
            for (int nt = 0; nt < 4; nt++) {
                b[nt][0] = __float_as_uint(Bs[(brow    ) * BSTRIDE + bcol + nt * 8]);
                b[nt][1] = __float_as_uint(Bs[(brow + 4) * BSTRIDE + bcol + nt * 8]);
            }
#pragma unroll
            for (int mt = 0; mt < 4; mt++)
#pragma unroll
                for (int nt = 0; nt < 4; nt++)
                    MMA_TF32(c[mt][nt], a[mt], b[nt]);
        }
        __syncthreads();
        p ^= 1;
    }

#pragma unroll
    for (int nt = 0; nt < 4; nt++) {
        int col = bn + wn + nt * 8 + 2 * (lane & 3);
        float2 bb = *(const float2*)&bias[col];
#pragma unroll
        for (int mt = 0; mt < 4; mt++) {
            int row0 = bm + wm + mt * 16 + (lane >> 2);
#pragma unroll
            for (int h = 0; h < 2; h++) {
                int row = row0 + h * 8;
                if (row < Mstore) {
                    float2 v;
                    v.x = c[mt][nt][2 * h]     + bb.x;
                    v.y = c[mt][nt][2 * h + 1] + bb.y;
                    if (EPI == 1) { v.x = gelu_f(v.x); v.y = gelu_f(v.y); }
                    size_t o = (size_t)row * N + col;
                    if (EPI == 2) {
                        float2 rv = *(const float2*)&res[o];
                        v.x += rv.x; v.y += rv.y;
                    }
                    if (CVT) { v.x = tf32r(v.x); v.y = tf32r(v.y); }
                    *(float2*)&Cd[o] = v;
                }
            }
        }
    }
}

/* ---------------- launch ------------------------------------------------ */
extern "C" void kernel_launch(void* const* d_in, const int* in_sizes, int n_in,
                              void* d_out, int out_size) {
    const float* x     = (const float*)d_in[0];
    const float* gt    = (const float*)d_in[1];
    const float* n1g   = (const float*)d_in[2];
    const float* n1b   = (const float*)d_in[3];
    const float* qkvw  = (const float*)d_in[4];
    const float* qkvb  = (const float*)d_in[5];
    const float* btab  = (const float*)d_in[6];
    const float* projw = (const float*)d_in[7];
    const float* projb = (const float*)d_in[8];
    const float* n2g   = (const float*)d_in[9];
    const float* n2b   = (const float*)d_in[10];
    const float* fc1w  = (const float*)d_in[11];
    const float* fc1b  = (const float*)d_in[12];
    const float* fc2w  = (const float*)d_in[13];
    const float* fc2b  = (const float*)d_in[14];
    float* out = (float*)d_out;

    float *xc, *qkv, *ao, *proj, *xres, *ln2b, *hb;
    float *wq, *wp, *w1, *w2;
    cudaGetSymbolAddress((void**)&xc,   g_xc);
    cudaGetSymbolAddress((void**)&qkv,  g_qkv);
    cudaGetSymbolAddress((void**)&ao,   g_attnout);
    cudaGetSymbolAddress((void**)&proj, g_proj);
    cudaGetSymbolAddress((void**)&xres, g_xres);
    cudaGetSymbolAddress((void**)&ln2b, g_ln2);
    cudaGetSymbolAddress((void**)&hb,   g_hid);
    cudaGetSymbolAddress((void**)&wq,   g_wqkv);
    cudaGetSymbolAddress((void**)&wp,   g_wproj);
    cudaGetSymbolAddress((void**)&w1,   g_wfc1);
    cudaGetSymbolAddress((void**)&w2,   g_wfc2);

    cudaFuncSetAttribute(attn_mma,
                         cudaFuncAttributeMaxDynamicSharedMemorySize,
                         ATT2_SMEM);
    cudaFuncSetAttribute(gemm_tc<0, 0>,
                         cudaFuncAttributeMaxDynamicSharedMemorySize,
                         GEMM_SMEM_BYTES);
    cudaFuncSetAttribute(gemm_tc<1, 1>,
                         cudaFuncAttributeMaxDynamicSharedMemorySize,
                         GEMM_SMEM_BYTES);
    cudaFuncSetAttribute(gemm_tc<2, 0>,
                         cudaFuncAttributeMaxDynamicSharedMemorySize,
                         GEMM_SMEM_BYTES);

    wconv<<<(C_ * 3 * C_ + 255) / 256, 256>>>(qkvw, wq, C_ * 3 * C_);
    wconv<<<(C_ * C_ + 255) / 256, 256>>>(projw, wp, C_ * C_);
    wconv<<<(C_ * HID + 255) / 256, 256>>>(fc1w, w1, C_ * HID);
    wconv<<<(HID * C_ + 255) / 256, 256>>>(fc2w, w2, HID * C_);

    bias_pre   <<<(NWIN * NWIN + 255) / 256, 256>>>(btab);
    gt_copy    <<<(NW * C_ + 255) / 256, 256>>>(gt);
    ln1_scatter<<<L_ / 8, 256>>>(x, n1g, n1b);

    gemm_tc<0, 0><<<dim3((3 * C_) / 128, M1 / 128), 256, GEMM_SMEM_BYTES>>>(
        xc, wq, qkvb, nullptr, qkv, M1, 3 * C_, C_);

    attn_mma<<<NW * HEADS, 256, ATT2_SMEM>>>();

    gemm_tc<0, 0><<<dim3(C_ / 128, M1 / 128), 256, GEMM_SMEM_BYTES>>>(
        ao, wp, projb, nullptr, proj, M1, C_, C_);

    unscatter_res<<<(L_ * C_) / 256, 256>>>(x);
    gt_out_copy  <<<(NW * C_ + 255) / 256, 256>>>(out);
    ln2_kernel   <<<L_ / 8, 256>>>(n2g, n2b);

    gemm_tc<1, 1><<<dim3(HID / 128, M1 / 128), 256, GEMM_SMEM_BYTES>>>(
        ln2b, w1, fc1b, nullptr, hb, M1, HID, C_);

    gemm_tc<2, 0><<<dim3(C_ / 128, M1 / 128), 256, GEMM_SMEM_BYTES>>>(
        hb, w2, fc2b, xres, out, L_, C_, HID);
}

// round 7
// speedup vs baseline: 2.8616x; 1.0118x over previous
#include <cuda_runtime.h>
#include <math.h>
#include <stdint.h>

#define S_ 7
#define H_ 56
#define W_ 56
#define WS 7
#define C_ 384
#define HEADS 12
#define NW 64
#define NTOK 344
#define NWIN 343
#define L_ (S_*H_*W_)          /* 21952 */
#define M1 (NW*NTOK)           /* 22016 */
#define HID 1536
#define EPS_LN 1e-5f
#define QSCALE 0.17677669529663687f  /* 32^-0.5 */

/* ---------------- scratch (static device globals; no allocation) -------- */
__device__ float g_xc     [(size_t)M1 * C_];
__device__ float g_qkv    [(size_t)M1 * 3 * C_];
__device__ float g_attnout[(size_t)M1 * C_];
__device__ float g_xres   [(size_t)L_ * C_];
__device__ float g_ln2    [(size_t)M1 * C_];
__device__ float g_hid    [(size_t)M1 * HID];
__device__ float g_bias   [(size_t)HEADS * NWIN * NWIN];
__device__ float g_wqkv   [(size_t)C_ * 3 * C_];
__device__ float g_wproj  [(size_t)C_ * C_];
__device__ float g_wfc1   [(size_t)C_ * HID];
__device__ float g_wfc2   [(size_t)HID * C_];

/* ---------------- helpers ---------------------------------------------- */
__device__ __forceinline__ float warp_sum(float v) {
    v += __shfl_xor_sync(0xffffffffu, v, 16);
    v += __shfl_xor_sync(0xffffffffu, v, 8);
    v += __shfl_xor_sync(0xffffffffu, v, 4);
    v += __shfl_xor_sync(0xffffffffu, v, 2);
    v += __shfl_xor_sync(0xffffffffu, v, 1);
    return v;
}
__device__ __forceinline__ float warp_max(float v) {
    v = fmaxf(v, __shfl_xor_sync(0xffffffffu, v, 16));
    v = fmaxf(v, __shfl_xor_sync(0xffffffffu, v, 8));
    v = fmaxf(v, __shfl_xor_sync(0xffffffffu, v, 4));
    v = fmaxf(v, __shfl_xor_sync(0xffffffffu, v, 2));
    v = fmaxf(v, __shfl_xor_sync(0xffffffffu, v, 1));
    return v;
}
__device__ __forceinline__ float gelu_f(float v) {
    return 0.5f * v * (1.f + erff(v * 0.7071067811865475f));
}
__device__ __forceinline__ float tf32r(float x) {
    uint32_t u;
    asm("cvt.rna.tf32.f32 %0, %1;" : "=r"(u) : "f"(x));
    return __uint_as_float(u);
}
__device__ __forceinline__ void cpa16(float* s, const float* g) {
    uint32_t sa = (uint32_t)__cvta_generic_to_shared(s);
    asm volatile("cp.async.cg.shared.global [%0], [%1], 16;\n" :: "r"(sa), "l"(g));
}
#define MMA_TF32(c4, a4, b2)                                                   \
    asm volatile(                                                              \
        "mma.sync.aligned.m16n8k8.row.col.f32.tf32.tf32.f32 "                  \
        "{%0,%1,%2,%3}, {%4,%5,%6,%7}, {%8,%9}, {%0,%1,%2,%3};\n"              \
        : "+f"((c4)[0]), "+f"((c4)[1]), "+f"((c4)[2]), "+f"((c4)[3])           \
        : "r"((a4)[0]), "r"((a4)[1]), "r"((a4)[2]), "r"((a4)[3]),              \
          "r"((b2)[0]), "r"((b2)[1]))

__device__ __forceinline__ int scatter_row(int l) {
    int s   = l / (H_ * W_);
    int rem = l % (H_ * W_);
    int h   = rem / W_;
    int w   = rem % W_;
    int s2 = (s >= 3) ? s - 3 : s + 4;
    int h2 = (h >= 3) ? h - 3 : h + 53;
    int w2 = (w >= 3) ? w - 3 : w + 53;
    int win = (h2 / WS) * 8 + (w2 / WS);
    int t   = s2 * 49 + (h2 % WS) * 7 + (w2 % WS);
    return win * NTOK + 1 + t;
}
/* inverse of scatter_row for t >= 1 */
__device__ __forceinline__ int unscatter_l(int win, int t) {
    int t0 = t - 1;
    int ts = t0 / 49, th = (t0 / 7) % 7, tw = t0 % 7;
    int wh = win >> 3, ww = win & 7;
    int h2 = wh * 7 + th, w2 = ww * 7 + tw;
    int s  = (ts <= 3) ? ts + 3 : ts - 4;
    int hh = (h2 <= 52) ? h2 + 3 : h2 - 53;
    int wo = (w2 <= 52) ? w2 + 3 : w2 - 53;
    return (s * H_ + hh) * W_ + wo;
}

/* ---------------- small kernels ----------------------------------------- */
__global__ void wconv4(const float* __restrict__ a, const float* __restrict__ b,
                       const float* __restrict__ c, const float* __restrict__ d,
                       float* __restrict__ oa, float* __restrict__ ob,
                       float* __restrict__ oc, float* __restrict__ od) {
    const int n1 = C_ * 3 * C_, n2 = C_ * C_, n3 = C_ * HID, n4 = HID * C_;
    int i = blockIdx.x * 256 + threadIdx.x;
    if (i < n1) { oa[i] = tf32r(a[i]); return; }
    i -= n1;
    if (i < n2) { ob[i] = tf32r(b[i]); return; }
    i -= n2;
    if (i < n3) { oc[i] = tf32r(c[i]); return; }
    i -= n3;
    if (i < n4) { od[i] = tf32r(d[i]); }
}

__global__ void bias_pre(const float* __restrict__ bt) {
    int idx = blockIdx.x * blockDim.x + threadIdx.x;
    if (idx >= NWIN * NWIN) return;
    int i = idx / NWIN, j = idx % NWIN;
    int si = i / 49, hi = (i / 7) % 7, wi = i % 7;
    int sj = j / 49, hj = (j / 7) % 7, wj = j % 7;
    int r = (si - sj + 6) * 20 + (hi - hj + 6) * 13 + (wi - wj + 6);
#pragma unroll
    for (int h = 0; h < HEADS; h++)
        g_bias[(size_t)h * NWIN * NWIN + idx] = bt[r * HEADS + h];
}

__global__ void gt_copy(const float* __restrict__ gt) {
    int idx = blockIdx.x * blockDim.x + threadIdx.x;
    if (idx >= NW * C_) return;
    int w = idx / C_, c = idx % C_;
    g_xc[((size_t)w * NTOK) * C_ + c] = tf32r(gt[idx]);
}

__global__ void ln1_scatter(const float* __restrict__ x,
                            const float* __restrict__ g,
                            const float* __restrict__ b) {
    int gw   = (blockIdx.x * blockDim.x + threadIdx.x) >> 5;
    int lane = threadIdx.x & 31;
    if (gw >= L_) return;
    const float* xi = x + (size_t)gw * C_;
    float v[12];
    float sum = 0.f;
#pragma unroll
    for (int m = 0; m < 12; m++) { v[m] = xi[lane + m * 32]; sum += v[m]; }
    sum = warp_sum(sum);
    float mu = sum * (1.f / 384.f);
    float vs = 0.f;
#pragma unroll
    for (int m = 0; m < 12; m++) { float d = v[m] - mu; vs += d * d; }
    vs = warp_sum(vs);
    float rstd = rsqrtf(vs * (1.f / 384.f) + EPS_LN);
    float* o = g_xc + (size_t)scatter_row(gw) * C_;
#pragma unroll
    for (int m = 0; m < 12; m++) {
        int c = lane + m * 32;
        o[c] = tf32r((v[m] - mu) * rstd * g[c] + b[c]);
    }
}

__global__ void ln2_kernel(const float* __restrict__ g,
                           const float* __restrict__ b) {
    int gw   = (blockIdx.x * blockDim.x + threadIdx.x) >> 5;
    int lane = threadIdx.x & 31;
    if (gw >= L_) return;
    const float* xi = g_xres + (size_t)gw * C_;
    float v[12];
    float sum = 0.f;
#pragma unroll
    for (int m = 0; m < 12; m++) { v[m] = xi[lane + m * 32]; sum += v[m]; }
    sum = warp_sum(sum);
    float mu = sum * (1.f / 384.f);
    float vs = 0.f;
#pragma unroll
    for (int m = 0; m < 12; m++) { float d = v[m] - mu; vs += d * d; }
    vs = warp_sum(vs);
    float rstd = rsqrtf(vs * (1.f / 384.f) + EPS_LN);
    float* o = g_ln2 + (size_t)gw * C_;
#pragma unroll
    for (int m = 0; m < 12; m++) {
        int c = lane + m * 32;
        o[c] = tf32r((v[m] - mu) * rstd * g[c] + b[c]);
    }
}

/* ---------------- attention via tf32 mma -------------------------------- */
#define KSTR 360
#define VSTR 40
#define SSTR 356
#define QSTR 36
#define NPAD 352
#define ATT2_SMEM ((32*KSTR + NTOK*VSTR + 64*SSTR + 64*QSTR) * 4 + NTOK * 4)

__global__ __launch_bounds__(256, 1) void attn_mma() {
    extern __shared__ float sm[];
    float* Ks = sm;
    float* Vs = Ks + 32 * KSTR;
    float* Ss = Vs + NTOK * VSTR;
    float* Qs = Ss + 64 * SSTR;
    int*  lab = (int*)(Qs + 64 * QSTR);

    int tid = threadIdx.x, lane = tid & 31, wid = tid >> 5;
    int win = blockIdx.x / HEADS, head = blockIdx.x % HEADS;
    const float* base = g_qkv + (size_t)win * NTOK * (3 * C_) + head * 32;

    for (int idx = tid; idx < 32 * NPAD; idx += 256) {
        int n = idx >> 5, d = idx & 31;
        float v = (n < NTOK) ? base[(size_t)n * (3 * C_) + C_ + d] : 0.f;
        Ks[d * KSTR + n] = tf32r(v);
    }
    for (int idx = tid; idx < NTOK * 32; idx += 256) {
        int j = idx >> 5, d = idx & 31;
        Vs[j * VSTR + d] = tf32r(base[(size_t)j * (3 * C_) + 2 * C_ + d]);
    }
    int wh = win >> 3, ww = win & 7;
    for (int t = tid; t < NTOK; t += 256) {
        int lv = -1;
        if (t > 0) {
            int t0 = t - 1;
            int ts = t0 / 49, th = (t0 / 7) % 7, tw = t0 % 7;
            int hh = wh * 7 + th, wc = ww * 7 + tw;
            int ia = (ts < 4) ? 1 : 2;
            int ib = (hh < 49) ? 0 : ((hh < 53) ? 1 : 2);
            int ic = (wc < 49) ? 0 : ((wc < 53) ? 1 : 2);
            lv = ia * 9 + ib * 3 + ic;
        }
        lab[t] = lv;
    }
    __syncthreads();

    const float* bh = g_bias + (size_t)head * NWIN * NWIN;
    const int wm  = (wid & 1) * 32;
    const int wn  = (wid >> 1) * 88;
    const int wnO = (wid >> 1) * 8;

    for (int qt = 0; qt < 6; qt++) {
        int qbase = qt * 64;
        for (int i = tid; i < 64 * 32; i += 256) {
            int m = i >> 5, d = i & 31;
            int r = qbase + m;
            float v = (r < NTOK) ? base[(size_t)r * (3 * C_) + d] * QSCALE : 0.f;
            Qs[m * QSTR + d] = tf32r(v);
        }
        __syncthreads();

        float c[2][11][4];
#pragma unroll
        for (int mt = 0; mt < 2; mt++)
#pragma unroll
            for (int nt = 0; nt < 11; nt++)
#pragma unroll
                for (int q = 0; q < 4; q++) c[mt][nt][q] = 0.f;

#pragma unroll
        for (int ks = 0; ks < 4; ks++) {
            uint32_t a[2][4];
            int acol = ks * 8 + (lane & 3);
#pragma unroll
            for (int mt = 0; mt < 2; mt++) {
                int r = wm + mt * 16 + (lane >> 2);
                a[mt][0] = __float_as_uint(Qs[(r    ) * QSTR + acol    ]);
                a[mt][1] = __float_as_uint(Qs[(r + 8) * QSTR + acol    ]);
                a[mt][2] = __float_as_uint(Qs[(r    ) * QSTR + acol + 4]);
                a[mt][3] = __float_as_uint(Qs[(r + 8) * QSTR + acol + 4]);
            }
#pragma unroll
            for (int nt = 0; nt < 11; nt++) {
                uint32_t b[2];
                int bc = wn + nt * 8 + (lane >> 2);
                b[0] = __float_as_uint(Ks[(ks * 8 + (lane & 3)    ) * KSTR + bc]);
                b[1] = __float_as_uint(Ks[(ks * 8 + (lane & 3) + 4) * KSTR + bc]);
                MMA_TF32(c[0][nt], a[0], b);
                MMA_TF32(c[1][nt], a[1], b);
            }
        }

#pragma unroll
        for (int mt = 0; mt < 2; mt++) {
            int r0 = wm + mt * 16 + (lane >> 2);
#pragma unroll
            for (int nt = 0; nt < 11; nt++) {
                int j0 = wn + nt * 8 + 2 * (lane & 3);
#pragma unroll
                for (int h = 0; h < 2; h++) {
                    int rr = r0 + h * 8;
                    int rg = qbase + rr;
                    float v0 = c[mt][nt][2 * h];
                    float v1 = c[mt][nt][2 * h + 1];
                    if (rg < NTOK && rg > 0) {
                        int lr = lab[rg];
                        if (j0 < NTOK && j0 > 0) {
                            v0 += bh[(rg - 1) * NWIN + (j0 - 1)];
                            if (lr != lab[j0]) v0 -= 100.f;
                        }
                        int j1 = j0 + 1;
                        if (j1 < NTOK) {
                            v1 += bh[(rg - 1) * NWIN + (j1 - 1)];
                            if (lr != lab[j1]) v1 -= 100.f;
                        }
                    }
                    if (j0 >= NTOK)     v0 = -1e30f;
                    if (j0 + 1 >= NTOK) v1 = -1e30f;
                    Ss[rr * SSTR + j0]     = v0;
                    Ss[rr * SSTR + j0 + 1] = v1;
                }
            }
        }
        __syncthreads();

#pragma unroll
        for (int i = 0; i < 8; i++) {
            int rr = wid * 8 + i;
            float s[11];
            float mx = -1e30f;
#pragma unroll
            for (int m = 0; m < 11; m++) {
                s[m] = Ss[rr * SSTR + lane + m * 32];
                mx = fmaxf(mx, s[m]);
            }
            mx = warp_max(mx);
            float sum = 0.f;
#pragma unroll
            for (int m = 0; m < 11; m++) {
                float e = __expf(s[m] - mx);
                s[m] = e; sum += e;
            }
            sum = warp_sum(sum);
            float inv = 1.f / sum;
#pragma unroll
            for (int m = 0; m < 11; m++)
                Ss[rr * SSTR + lane + m * 32] = tf32r(s[m] * inv);
        }
        __syncthreads();

        float o[2][4] = {};
#pragma unroll 4
        for (int kt = 0; kt < 43; kt++) {
            uint32_t b[2];
            int kr = kt * 8 + (lane & 3);
            int bc = wnO + (lane >> 2);
            b[0] = __float_as_uint(Vs[(kr    ) * VSTR + bc]);
            b[1] = __float_as_uint(Vs[(kr + 4) * VSTR + bc]);
#pragma unroll
            for (int mt = 0; mt < 2; mt++) {
                uint32_t a[4];
                int r  = wm + mt * 16 + (lane >> 2);
                int ac = kt * 8 + (lane & 3);
                a[0] = __float_as_uint(Ss[(r    ) * SSTR + ac    ]);
                a[1] = __float_as_uint(Ss[(r + 8) * SSTR + ac    ]);
                a[2] = __float_as_uint(Ss[(r    ) * SSTR + ac + 4]);
                a[3] = __float_as_uint(Ss[(r + 8) * SSTR + ac + 4]);
                MMA_TF32(o[mt], a, b);
            }
        }
#pragma unroll
        for (int mt = 0; mt < 2; mt++)
#pragma unroll
            for (int h = 0; h < 2; h++) {
                int rr = qbase + wm + mt * 16 + (lane >> 2) + h * 8;
                if (rr < NTOK) {
                    float2 v;
                    v.x = tf32r(o[mt][2 * h]);
                    v.y = tf32r(o[mt][2 * h + 1]);
                    *(float2*)&g_attnout[((size_t)win * NTOK + rr) * C_ +
                                         head * 32 + wnO + 2 * (lane & 3)] = v;
                }
            }
        __syncthreads();
    }
}

/* ---------------- TF32 tensor-core GEMM, 3-stage cp.async --------------- */
/* EPI: 0 none, 1 gelu, 2 +res->Cd, 3 swin-unscatter (Cd=xres, res=x,
   gtout=out tail).  CVT: tf32-round stores.                               */
#define ASTRIDE 36
#define BSTRIDE 136
#define ABUF 4608
#define BBUF 4352
#define STG (ABUF + BBUF)
#define GEMM_SMEM_BYTES (3 * STG * 4)   /* 107520 */

template<int EPI, int CVT>
__global__ __launch_bounds__(256, 2) void gemm_tc(const float* __restrict__ A,
                                                  const float* __restrict__ B,
                                                  const float* __restrict__ bias,
                                                  const float* __restrict__ res,
                                                  float* __restrict__ Cd,
                                                  float* __restrict__ gtout,
                                                  int Mstore, int N, int K) {
    extern __shared__ float sm[];
    const int tid = threadIdx.x, lane = tid & 31, wid = tid >> 5;
    const int bm = blockIdx.y * 128, bn = blockIdx.x * 128;
    const int wm = (wid & 1) * 64, wn = (wid >> 1) * 32;

    float c[4][4][4];
#pragma unroll
    for (int i = 0; i < 4; i++)
#pragma unroll
        for (int j = 0; j < 4; j++)
#pragma unroll
            for (int k = 0; k < 4; k++) c[i][j][k] = 0.f;

    const int NK = K >> 5;

    auto issue = [&](int kt) {
        int p = kt % 3;
        float* As = sm + p * STG;
        float* Bs = As + ABUF;
        const float* Ag = A + (size_t)bm * K + kt * 32;
        const float* Bg = B + (size_t)(kt * 32) * N + bn;
#pragma unroll
        for (int i = 0; i < 4; i++) {
            int idx = tid + i * 256;
            int r = idx >> 3, c4 = (idx & 7) * 4;
            cpa16(As + r * ASTRIDE + c4, Ag + (size_t)r * K + c4);
        }
#pragma unroll
        for (int i = 0; i < 4; i++) {
            int idx = tid + i * 256;
            int r = idx >> 5, cc = (idx & 31) * 4;
            cpa16(Bs + r * BSTRIDE + cc, Bg + (size_t)r * N + cc);
        }
        asm volatile("cp.async.commit_group;\n");
    };

    issue(0);
    if (NK > 1) issue(1);

    for (int kt = 0; kt < NK; kt++) {
        if (kt + 1 < NK)
            asm volatile("cp.async.wait_group 1;\n");
        else
            asm volatile("cp.async.wait_group 0;\n");
        __syncthreads();
        if (kt + 2 < NK) issue(kt + 2);

        const int p = kt % 3;
        const float* As = sm + p * STG;
        const float* Bs = As + ABUF;
#pragma unroll
        for (int ks = 0; ks < 4; ks++) {
            uint32_t a[4][4], b[4][2];
            int arow = wm + (lane >> 2);
            int acol = ks * 8 + (lane & 3);
#pragma unroll
            for (int mt = 0; mt < 4; mt++) {
                int r = arow + mt * 16;
                a[mt][0] = __float_as_uint(As[(r    ) * ASTRIDE + acol    ]);
                a[mt][1] = __float_as_uint(As[(r + 8) * ASTRIDE + acol    ]);
                a[mt][2] = __float_as_uint(As[(r    ) * ASTRIDE + acol + 4]);
                a[mt][3] = __float_as_uint(As[(r + 8) * ASTRIDE + acol + 4]);
            }
            int brow = ks * 8 + (lane & 3);
            int bcol = wn + (lane >> 2);
#pragma unroll
            for (int nt = 0; nt < 4; nt++) {
                b[nt][0] = __float_as_uint(Bs[(brow    ) * BSTRIDE + bcol + nt * 8]);
                b[nt][1] = __float_as_uint(Bs[(brow + 4) * BSTRIDE + bcol + nt * 8]);
            }
#pragma unroll
            for (int mt = 0; mt < 4; mt++)
#pragma unroll
                for (int nt = 0; nt < 4; nt++)
                    MMA_TF32(c[mt][nt], a[mt], b[nt]);
        }
        __syncthreads();
    }

    if (EPI == 3) {
        /* fused unscatter + residual + gt_out routing */
#pragma unroll
        for (int mt = 0; mt < 4; mt++)
#pragma unroll
            for (int h = 0; h < 2; h++) {
                int row = bm + wm + mt * 16 + (lane >> 2) + h * 8;
                int win = row / NTOK, t = row % NTOK;
                float* dst;
                const float* xsrc = nullptr;
                if (t == 0) {
                    dst = gtout + (size_t)win * C_;
                } else {
                    int l = unscatter_l(win, t);
                    dst  = Cd  + (size_t)l * C_;
                    xsrc = res + (size_t)l * C_;
                }
#pragma unroll
                for (int nt = 0; nt < 4; nt++) {
                    int col = bn + wn + nt * 8 + 2 * (lane & 3);
                    float2 bb = *(const float2*)&bias[col];
                    float2 v;
                    v.x = c[mt][nt][2 * h]     + bb.x;
                    v.y = c[mt][nt][2 * h + 1] + bb.y;
                    if (xsrc) {
                        float2 rv = *(const float2*)&xsrc[col];
                        v.x += rv.x; v.y += rv.y;
                    }
                    *(float2*)&dst[col] = v;
                }
            }
    } else {
#pragma unroll
        for (int nt = 0; nt < 4; nt++) {
            int col = bn + wn + nt * 8 + 2 * (lane & 3);
            float2 bb = *(const float2*)&bias[col];
#pragma unroll
            for (int mt = 0; mt < 4; mt++) {
                int row0 = bm + wm + mt * 16 + (lane >> 2);
#pragma unroll
                for (int h = 0; h < 2; h++) {
                    int row = row0 + h * 8;
                    if (row < Mstore) {
                        float2 v;
                        v.x = c[mt][nt][2 * h]     + bb.x;
                        v.y = c[mt][nt][2 * h + 1] + bb.y;
                        if (EPI == 1) { v.x = gelu_f(v.x); v.y = gelu_f(v.y); }
                        size_t o = (size_t)row * N + col;
                        if (EPI == 2) {
                            float2 rv = *(const float2*)&res[o];
                            v.x += rv.x; v.y += rv.y;
                        }
                        if (CVT) { v.x = tf32r(v.x); v.y = tf32r(v.y); }
                        *(float2*)&Cd[o] = v;
                    }
                }
            }
        }
    }
}

/* ---------------- launch ------------------------------------------------ */
extern "C" void kernel_launch(void* const* d_in, const int* in_sizes, int n_in,
                              void* d_out, int out_size) {
    const float* x     = (const float*)d_in[0];
    const float* gt    = (const float*)d_in[1];
    const float* n1g   = (const float*)d_in[2];
    const float* n1b   = (const float*)d_in[3];
    const float* qkvw  = (const float*)d_in[4];
    const float* qkvb  = (const float*)d_in[5];
    const float* btab  = (const float*)d_in[6];
    const float* projw = (const float*)d_in[7];
    const float* projb = (const float*)d_in[8];
    const float* n2g   = (const float*)d_in[9];
    const float* n2b   = (const float*)d_in[10];
    const float* fc1w  = (const float*)d_in[11];
    const float* fc1b  = (const float*)d_in[12];
    const float* fc2w  = (const float*)d_in[13];
    const float* fc2b  = (const float*)d_in[14];
    float* out = (float*)d_out;

    float *xc, *qkv, *ao, *xres, *ln2b, *hb;
    float *wq, *wp, *w1, *w2;
    cudaGetSymbolAddress((void**)&xc,   g_xc);
    cudaGetSymbolAddress((void**)&qkv,  g_qkv);
    cudaGetSymbolAddress((void**)&ao,   g_attnout);
    cudaGetSymbolAddress((void**)&xres, g_xres);
    cudaGetSymbolAddress((void**)&ln2b, g_ln2);
    cudaGetSymbolAddress((void**)&hb,   g_hid);
    cudaGetSymbolAddress((void**)&wq,   g_wqkv);
    cudaGetSymbolAddress((void**)&wp,   g_wproj);
    cudaGetSymbolAddress((void**)&w1,   g_wfc1);
    cudaGetSymbolAddress((void**)&w2,   g_wfc2);

    cudaFuncSetAttribute(attn_mma,
                         cudaFuncAttributeMaxDynamicSharedMemorySize,
                         ATT2_SMEM);
    cudaFuncSetAttribute(gemm_tc<0, 0>,
                         cudaFuncAttributeMaxDynamicSharedMemorySize,
                         GEMM_SMEM_BYTES);
    cudaFuncSetAttribute(gemm_tc<1, 1>,
                         cudaFuncAttributeMaxDynamicSharedMemorySize,
                         GEMM_SMEM_BYTES);
    cudaFuncSetAttribute(gemm_tc<2, 0>,
                         cudaFuncAttributeMaxDynamicSharedMemorySize,
                         GEMM_SMEM_BYTES);
    cudaFuncSetAttribute(gemm_tc<3, 0>,
                         cudaFuncAttributeMaxDynamicSharedMemorySize,
                         GEMM_SMEM_BYTES);

    {
        const int ntot = C_ * 3 * C_ + C_ * C_ + C_ * HID + HID * C_;
        wconv4<<<(ntot + 255) / 256, 256>>>(qkvw, projw, fc1w, fc2w,
                                            wq, wp, w1, w2);
    }
    bias_pre   <<<(NWIN * NWIN + 255) / 256, 256>>>(btab);
    gt_copy    <<<(NW * C_ + 255) / 256, 256>>>(gt);
    ln1_scatter<<<L_ / 8, 256>>>(x, n1g, n1b);

    gemm_tc<0, 0><<<dim3((3 * C_) / 128, M1 / 128), 256, GEMM_SMEM_BYTES>>>(
        xc, wq, qkvb, nullptr, qkv, nullptr, M1, 3 * C_, C_);

    attn_mma<<<NW * HEADS, 256, ATT2_SMEM>>>();

    /* proj + fused unscatter/residual/gt_out */
    gemm_tc<3, 0><<<dim3(C_ / 128, M1 / 128), 256, GEMM_SMEM_BYTES>>>(
        ao, wp, projb, x, xres, out + (size_t)L_ * C_, M1, C_, C_);

    ln2_kernel<<<L_ / 8, 256>>>(n2g, n2b);

    gemm_tc<1, 1><<<dim3(HID / 128, M1 / 128), 256, GEMM_SMEM_BYTES>>>(
        ln2b, w1, fc1b, nullptr, hb, nullptr, M1, HID, C_);

    gemm_tc<2, 0><<<dim3(C_ / 128, L_ / 64 / 2 + ((L_ % 128) ? 1 : 0)), 256,
                    GEMM_SMEM_BYTES>>>(
        hb, w2, fc2b, xres, out, nullptr, L_, C_, HID);
}

// round 8
// speedup vs baseline: 2.9678x; 1.0371x over previous
#include <cuda_runtime.h>
#include <math.h>
#include <stdint.h>

#define S_ 7
#define H_ 56
#define W_ 56
#define WS 7
#define C_ 384
#define HEADS 12
#define NW 64
#define NTOK 344
#define NWIN 343
#define L_ (S_*H_*W_)          /* 21952 */
#define M1 (NW*NTOK)           /* 22016 */
#define HID 1536
#define EPS_LN 1e-5f
#define QSCALE 0.17677669529663687f  /* 32^-0.5 */

/* ---------------- scratch (static device globals; no allocation) -------- */
__device__ float g_xc     [(size_t)M1 * C_];
__device__ float g_qkv    [(size_t)M1 * 3 * C_];
__device__ float g_attnout[(size_t)M1 * C_];
__device__ float g_xres   [(size_t)L_ * C_];
__device__ float g_ln2    [(size_t)M1 * C_];
__device__ float g_hid    [(size_t)M1 * HID];
__device__ float g_bias   [(size_t)HEADS * NWIN * NWIN];
__device__ float g_wqkv   [(size_t)C_ * 3 * C_];   /* W^T [N][K] tf32 */
__device__ float g_wproj  [(size_t)C_ * C_];
__device__ float g_wfc1   [(size_t)C_ * HID];
__device__ float g_wfc2   [(size_t)HID * C_];

/* ---------------- helpers ---------------------------------------------- */
__device__ __forceinline__ float warp_sum(float v) {
    v += __shfl_xor_sync(0xffffffffu, v, 16);
    v += __shfl_xor_sync(0xffffffffu, v, 8);
    v += __shfl_xor_sync(0xffffffffu, v, 4);
    v += __shfl_xor_sync(0xffffffffu, v, 2);
    v += __shfl_xor_sync(0xffffffffu, v, 1);
    return v;
}
__device__ __forceinline__ float warp_max(float v) {
    v = fmaxf(v, __shfl_xor_sync(0xffffffffu, v, 16));
    v = fmaxf(v, __shfl_xor_sync(0xffffffffu, v, 8));
    v = fmaxf(v, __shfl_xor_sync(0xffffffffu, v, 4));
    v = fmaxf(v, __shfl_xor_sync(0xffffffffu, v, 2));
    v = fmaxf(v, __shfl_xor_sync(0xffffffffu, v, 1));
    return v;
}
__device__ __forceinline__ float gelu_f(float v) {
    return 0.5f * v * (1.f + erff(v * 0.7071067811865475f));
}
__device__ __forceinline__ float tf32r(float x) {
    uint32_t u;
    asm("cvt.rna.tf32.f32 %0, %1;" : "=r"(u) : "f"(x));
    return __uint_as_float(u);
}
__device__ __forceinline__ void cpa16(float* s, const float* g) {
    uint32_t sa = (uint32_t)__cvta_generic_to_shared(s);
    asm volatile("cp.async.cg.shared.global [%0], [%1], 16;\n" :: "r"(sa), "l"(g));
}
#define MMA_TF32(c4, a4, b2)                                                   \
    asm volatile(                                                              \
        "mma.sync.aligned.m16n8k8.row.col.f32.tf32.tf32.f32 "                  \
        "{%0,%1,%2,%3}, {%4,%5,%6,%7}, {%8,%9}, {%0,%1,%2,%3};\n"              \
        : "+f"((c4)[0]), "+f"((c4)[1]), "+f"((c4)[2]), "+f"((c4)[3])           \
        : "r"((a4)[0]), "r"((a4)[1]), "r"((a4)[2]), "r"((a4)[3]),              \
          "r"((b2)[0]), "r"((b2)[1]))
#define LDSM4(r0, r1, r2, r3, addr)                                            \
    asm volatile("ldmatrix.sync.aligned.m8n8.x4.shared.b16 {%0,%1,%2,%3}, [%4];" \
                 : "=r"(r0), "=r"(r1), "=r"(r2), "=r"(r3) : "r"(addr))
#define LDSM2(r0, r1, addr)                                                    \
    asm volatile("ldmatrix.sync.aligned.m8n8.x2.shared.b16 {%0,%1}, [%2];"     \
                 : "=r"(r0), "=r"(r1) : "r"(addr))

__device__ __forceinline__ int scatter_row(int l) {
    int s   = l / (H_ * W_);
    int rem = l % (H_ * W_);
    int h   = rem / W_;
    int w   = rem % W_;
    int s2 = (s >= 3) ? s - 3 : s + 4;
    int h2 = (h >= 3) ? h - 3 : h + 53;
    int w2 = (w >= 3) ? w - 3 : w + 53;
    int win = (h2 / WS) * 8 + (w2 / WS);
    int t   = s2 * 49 + (h2 % WS) * 7 + (w2 % WS);
    return win * NTOK + 1 + t;
}
__device__ __forceinline__ int unscatter_l(int win, int t) {
    int t0 = t - 1;
    int ts = t0 / 49, th = (t0 / 7) % 7, tw = t0 % 7;
    int wh = win >> 3, ww = win & 7;
    int h2 = wh * 7 + th, w2 = ww * 7 + tw;
    int s  = (ts <= 3) ? ts + 3 : ts - 4;
    int hh = (h2 <= 52) ? h2 + 3 : h2 - 53;
    int wo = (w2 <= 52) ? w2 + 3 : w2 - 53;
    return (s * H_ + hh) * W_ + wo;
}

/* ---------------- small kernels ----------------------------------------- */
/* tiled transpose + tf32 round: o[n*K + k] = tf32r(w[k*N + n]) */
__global__ void wtrans(const float* __restrict__ w, float* __restrict__ o,
                       int K, int N) {
    __shared__ float t[32][33];
    int bn = blockIdx.x * 32, bk = blockIdx.y * 32;
    int tx = threadIdx.x, ty = threadIdx.y;
#pragma unroll
    for (int i = 0; i < 32; i += 8)
        t[ty + i][tx] = w[(size_t)(bk + ty + i) * N + bn + tx];
    __syncthreads();
#pragma unroll
    for (int i = 0; i < 32; i += 8)
        o[(size_t)(bn + ty + i) * K + bk + tx] = tf32r(t[tx][ty + i]);
}

__global__ void bias_pre(const float* __restrict__ bt) {
    int idx = blockIdx.x * blockDim.x + threadIdx.x;
    if (idx >= NWIN * NWIN) return;
    int i = idx / NWIN, j = idx % NWIN;
    int si = i / 49, hi = (i / 7) % 7, wi = i % 7;
    int sj = j / 49, hj = (j / 7) % 7, wj = j % 7;
    int r = (si - sj + 6) * 20 + (hi - hj + 6) * 13 + (wi - wj + 6);
#pragma unroll
    for (int h = 0; h < HEADS; h++)
        g_bias[(size_t)h * NWIN * NWIN + idx] = bt[r * HEADS + h];
}

__global__ void gt_copy(const float* __restrict__ gt) {
    int idx = blockIdx.x * blockDim.x + threadIdx.x;
    if (idx >= NW * C_) return;
    int w = idx / C_, c = idx % C_;
    g_xc[((size_t)w * NTOK) * C_ + c] = tf32r(gt[idx]);
}

__global__ void ln1_scatter(const float* __restrict__ x,
                            const float* __restrict__ g,
                            const float* __restrict__ b) {
    int gw   = (blockIdx.x * blockDim.x + threadIdx.x) >> 5;
    int lane = threadIdx.x & 31;
    if (gw >= L_) return;
    const float* xi = x + (size_t)gw * C_;
    float v[12];
    float sum = 0.f;
#pragma unroll
    for (int m = 0; m < 12; m++) { v[m] = xi[lane + m * 32]; sum += v[m]; }
    sum = warp_sum(sum);
    float mu = sum * (1.f / 384.f);
    float vs = 0.f;
#pragma unroll
    for (int m = 0; m < 12; m++) { float d = v[m] - mu; vs += d * d; }
    vs = warp_sum(vs);
    float rstd = rsqrtf(vs * (1.f / 384.f) + EPS_LN);
    float* o = g_xc + (size_t)scatter_row(gw) * C_;
#pragma unroll
    for (int m = 0; m < 12; m++) {
        int c = lane + m * 32;
        o[c] = tf32r((v[m] - mu) * rstd * g[c] + b[c]);
    }
}

__global__ void ln2_kernel(const float* __restrict__ g,
                           const float* __restrict__ b) {
    int gw   = (blockIdx.x * blockDim.x + threadIdx.x) >> 5;
    int lane = threadIdx.x & 31;
    if (gw >= L_) return;
    const float* xi = g_xres + (size_t)gw * C_;
    float v[12];
    float sum = 0.f;
#pragma unroll
    for (int m = 0; m < 12; m++) { v[m] = xi[lane + m * 32]; sum += v[m]; }
    sum = warp_sum(sum);
    float mu = sum * (1.f / 384.f);
    float vs = 0.f;
#pragma unroll
    for (int m = 0; m < 12; m++) { float d = v[m] - mu; vs += d * d; }
    vs = warp_sum(vs);
    float rstd = rsqrtf(vs * (1.f / 384.f) + EPS_LN);
    float* o = g_ln2 + (size_t)gw * C_;
#pragma unroll
    for (int m = 0; m < 12; m++) {
        int c = lane + m * 32;
        o[c] = tf32r((v[m] - mu) * rstd * g[c] + b[c]);
    }
}

/* ---------------- attention via tf32 mma + ldmatrix --------------------- */
/* smem: Ks [NPAD][KSTR] (n-major, tf32), Vs [NTOK][VSTR], Ss [64][SSTR],
   Qs [64][QSTR], lab[NTOK].  KSTR/QSTR mod32==4, SSTR mod32==4 ->
   ldmatrix rows hit 32 distinct banks.                                    */
#define KSTR 36
#define VSTR 40
#define SSTR 356
#define QSTR 36
#define NPAD 352
#define ATT2_SMEM ((NPAD*KSTR + NTOK*VSTR + 64*SSTR + 64*QSTR) * 4 + NTOK * 4)

__global__ __launch_bounds__(256, 1) void attn_mma() {
    extern __shared__ float sm[];
    float* Ks = sm;
    float* Vs = Ks + NPAD * KSTR;
    float* Ss = Vs + NTOK * VSTR;
    float* Qs = Ss + 64 * SSTR;
    int*  lab = (int*)(Qs + 64 * QSTR);

    int tid = threadIdx.x, lane = tid & 31, wid = tid >> 5;
    int win = blockIdx.x / HEADS, head = blockIdx.x % HEADS;
    const float* base = g_qkv + (size_t)win * NTOK * (3 * C_) + head * 32;

    uint32_t ks_s = (uint32_t)__cvta_generic_to_shared(Ks);
    uint32_t ss_s = (uint32_t)__cvta_generic_to_shared(Ss);
    uint32_t qs_s = (uint32_t)__cvta_generic_to_shared(Qs);

    /* K (n-major, zero pad rows), V */
    for (int idx = tid; idx < NPAD * 32; idx += 256) {
        int n = idx >> 5, d = idx & 31;
        Ks[n * KSTR + d] = (n < NTOK) ? tf32r(base[(size_t)n * (3 * C_) + C_ + d]) : 0.f;
    }
    for (int idx = tid; idx < NTOK * 32; idx += 256) {
        int j = idx >> 5, d = idx & 31;
        Vs[j * VSTR + d] = tf32r(base[(size_t)j * (3 * C_) + 2 * C_ + d]);
    }
    int wh = win >> 3, ww = win & 7;
    for (int t = tid; t < NTOK; t += 256) {
        int lv = -1;
        if (t > 0) {
            int t0 = t - 1;
            int ts = t0 / 49, th = (t0 / 7) % 7, tw = t0 % 7;
            int hh = wh * 7 + th, wc = ww * 7 + tw;
            int ia = (ts < 4) ? 1 : 2;
            int ib = (hh < 49) ? 0 : ((hh < 53) ? 1 : 2);
            int ic = (wc < 49) ? 0 : ((wc < 53) ? 1 : 2);
            lv = ia * 9 + ib * 3 + ic;
        }
        lab[t] = lv;
    }
    __syncthreads();

    const float* bh = g_bias + (size_t)head * NWIN * NWIN;
    const int wm  = (wid & 1) * 32;
    const int wn  = (wid >> 1) * 88;
    const int wnO = (wid >> 1) * 8;

    /* ldmatrix per-lane row/col offsets */
    const int r_off = (lane & 7) + ((lane >> 3) & 1) * 8;   /* a-frag rows  */
    const int a_k4  = ((lane >> 4) & 1) * 4;                /* a-frag col+4 */
    const int b_n   = (lane & 7) + ((lane >> 4) & 1) * 8;   /* b-frag rows  */
    const int b_k4  = ((lane >> 3) & 1) * 4;                /* b-frag col+4 */

    for (int qt = 0; qt < 6; qt++) {
        int qbase = qt * 64;
        for (int i = tid; i < 64 * 32; i += 256) {
            int m = i >> 5, d = i & 31;
            int r = qbase + m;
            float v = (r < NTOK) ? base[(size_t)r * (3 * C_) + d] * QSCALE : 0.f;
            Qs[m * QSTR + d] = tf32r(v);
        }
        __syncthreads();

        /* ---- S = Q K^T ---- */
        float c[2][11][4];
#pragma unroll
        for (int mt = 0; mt < 2; mt++)
#pragma unroll
            for (int nt = 0; nt < 11; nt++)
#pragma unroll
                for (int q = 0; q < 4; q++) c[mt][nt][q] = 0.f;

#pragma unroll
        for (int ks = 0; ks < 4; ks++) {
            uint32_t a[2][4], b[11][2];
#pragma unroll
            for (int mt = 0; mt < 2; mt++)
                LDSM4(a[mt][0], a[mt][1], a[mt][2], a[mt][3],
                      qs_s + ((wm + mt * 16 + r_off) * QSTR + ks * 8 + a_k4) * 4);
#pragma unroll
            for (int p = 0; p < 5; p++)
                LDSM4(b[2 * p][0], b[2 * p][1], b[2 * p + 1][0], b[2 * p + 1][1],
                      ks_s + ((wn + p * 16 + b_n) * KSTR + ks * 8 + b_k4) * 4);
            LDSM2(b[10][0], b[10][1],
                  ks_s + ((wn + 80 + (b_n & 7)) * KSTR + ks * 8 + b_k4) * 4);
#pragma unroll
            for (int nt = 0; nt < 11; nt++) {
                MMA_TF32(c[0][nt], a[0], b[nt]);
                MMA_TF32(c[1][nt], a[1], b[nt]);
            }
        }

        /* ---- store S + bias + mask ---- */
#pragma unroll
        for (int mt = 0; mt < 2; mt++) {
            int r0 = wm + mt * 16 + (lane >> 2);
#pragma unroll
            for (int nt = 0; nt < 11; nt++) {
                int j0 = wn + nt * 8 + 2 * (lane & 3);
#pragma unroll
                for (int h = 0; h < 2; h++) {
                    int rr = r0 + h * 8;
                    int rg = qbase + rr;
                    float v0 = c[mt][nt][2 * h];
                    float v1 = c[mt][nt][2 * h + 1];
                    if (rg < NTOK && rg > 0) {
                        int lr = lab[rg];
                        if (j0 < NTOK && j0 > 0) {
                            v0 += bh[(rg - 1) * NWIN + (j0 - 1)];
                            if (lr != lab[j0]) v0 -= 100.f;
                        }
                        int j1 = j0 + 1;
                        if (j1 < NTOK) {
                            v1 += bh[(rg - 1) * NWIN + (j1 - 1)];
                            if (lr != lab[j1]) v1 -= 100.f;
                        }
                    }
                    if (j0 >= NTOK)     v0 = -1e30f;
                    if (j0 + 1 >= NTOK) v1 = -1e30f;
                    Ss[rr * SSTR + j0]     = v0;
                    Ss[rr * SSTR + j0 + 1] = v1;
                }
            }
        }
        __syncthreads();

        /* ---- softmax, write P tf32 ---- */
#pragma unroll
        for (int i = 0; i < 8; i++) {
            int rr = wid * 8 + i;
            float s[11];
            float mx = -1e30f;
#pragma unroll
            for (int m = 0; m < 11; m++) {
                s[m] = Ss[rr * SSTR + lane + m * 32];
                mx = fmaxf(mx, s[m]);
            }
            mx = warp_max(mx);
            float sum = 0.f;
#pragma unroll
            for (int m = 0; m < 11; m++) {
                float e = __expf(s[m] - mx);
                s[m] = e; sum += e;
            }
            sum = warp_sum(sum);
            float inv = 1.f / sum;
#pragma unroll
            for (int m = 0; m < 11; m++)
                Ss[rr * SSTR + lane + m * 32] = tf32r(s[m] * inv);
        }
        __syncthreads();

        /* ---- O = P V ---- */
        float o[2][4] = {};
#pragma unroll 4
        for (int kt = 0; kt < 43; kt++) {
            uint32_t b[2];
            int kr = kt * 8 + (lane & 3);
            int bc = wnO + (lane >> 2);
            b[0] = __float_as_uint(Vs[(kr    ) * VSTR + bc]);
            b[1] = __float_as_uint(Vs[(kr + 4) * VSTR + bc]);
#pragma unroll
            for (int mt = 0; mt < 2; mt++) {
                uint32_t a[4];
                LDSM4(a[0], a[1], a[2], a[3],
                      ss_s + ((wm + mt * 16 + r_off) * SSTR + kt * 8 + a_k4) * 4);
                MMA_TF32(o[mt], a, b);
            }
        }
#pragma unroll
        for (int mt = 0; mt < 2; mt++)
#pragma unroll
            for (int h = 0; h < 2; h++) {
                int rr = qbase + wm + mt * 16 + (lane >> 2) + h * 8;
                if (rr < NTOK) {
                    float2 v;
                    v.x = tf32r(o[mt][2 * h]);
                    v.y = tf32r(o[mt][2 * h + 1]);
                    *(float2*)&g_attnout[((size_t)win * NTOK + rr) * C_ +
                                         head * 32 + wnO + 2 * (lane & 3)] = v;
                }
            }
        __syncthreads();
    }
}

/* ---------------- TF32 tensor-core GEMM (ldmatrix, 3-stage) ------------- */
/* A [M][K] row-major; B = W^T [N][K] (n-major).
   smem: As [128][36], Bs [128][36] per stage; both mod32==4 strides.
   EPI: 0 none, 1 gelu, 2 +res->Cd, 3 swin-unscatter.                      */
#define ASTR 36
#define BSTR 36
#define ABUF (128*ASTR)
#define STG  (2*ABUF)
#define GEMM_SMEM_BYTES (3 * STG * 4)   /* 110592 */

template<int EPI, int CVT>
__global__ __launch_bounds__(256, 2) void gemm_tc(const float* __restrict__ A,
                                                  const float* __restrict__ Bt,
                                                  const float* __restrict__ bias,
                                                  const float* __restrict__ res,
                                                  float* __restrict__ Cd,
                                                  float* __restrict__ gtout,
                                                  int Mstore, int N, int K) {
    extern __shared__ float sm[];
    const int tid = threadIdx.x, lane = tid & 31, wid = tid >> 5;
    const int bm = blockIdx.y * 128, bn = blockIdx.x * 128;
    const int wm = (wid & 1) * 64, wn = (wid >> 1) * 32;
    const uint32_t sm_s = (uint32_t)__cvta_generic_to_shared(sm);

    const int r_off = (lane & 7) + ((lane >> 3) & 1) * 8;
    const int a_k4  = ((lane >> 4) & 1) * 4;
    const int b_n   = (lane & 7) + ((lane >> 4) & 1) * 8;
    const int b_k4  = ((lane >> 3) & 1) * 4;

    float c[4][4][4];
#pragma unroll
    for (int i = 0; i < 4; i++)
#pragma unroll
        for (int j = 0; j < 4; j++)
#pragma unroll
            for (int k = 0; k < 4; k++) c[i][j][k] = 0.f;

    const int NK = K >> 5;

    auto issue = [&](int kt) {
        int p = kt % 3;
        float* As = sm + p * STG;
        float* Bs = As + ABUF;
        const float* Ag = A  + (size_t)bm * K + kt * 32;
        const float* Bg = Bt + (size_t)bn * K + kt * 32;
#pragma unroll
        for (int i = 0; i < 4; i++) {
            int idx = tid + i * 256;
            int r = idx >> 3, c4 = (idx & 7) * 4;
            cpa16(As + r * ASTR + c4, Ag + (size_t)r * K + c4);
        }
#pragma unroll
        for (int i = 0; i < 4; i++) {
            int idx = tid + i * 256;
            int r = idx >> 3, c4 = (idx & 7) * 4;
            cpa16(Bs + r * BSTR + c4, Bg + (size_t)r * K + c4);
        }
        asm volatile("cp.async.commit_group;\n");
    };

    issue(0);
    if (NK > 1) issue(1);

    for (int kt = 0; kt < NK; kt++) {
        if (kt + 1 < NK)
            asm volatile("cp.async.wait_group 1;\n");
        else
            asm volatile("cp.async.wait_group 0;\n");
        __syncthreads();
        if (kt + 2 < NK) issue(kt + 2);

        const int p = kt % 3;
        const uint32_t as_s = sm_s + p * STG * 4;
        const uint32_t bs_s = as_s + ABUF * 4;
#pragma unroll
        for (int ks = 0; ks < 4; ks++) {
            uint32_t a[4][4], b[4][2];
#pragma unroll
            for (int mt = 0; mt < 4; mt++)
                LDSM4(a[mt][0], a[mt][1], a[mt][2], a[mt][3],
                      as_s + ((wm + mt * 16 + r_off) * ASTR + ks * 8 + a_k4) * 4);
#pragma unroll
            for (int pp = 0; pp < 2; pp++)
                LDSM4(b[2 * pp][0], b[2 * pp][1], b[2 * pp + 1][0], b[2 * pp + 1][1],
                      bs_s + ((wn + pp * 16 + b_n) * BSTR + ks * 8 + b_k4) * 4);
#pragma unroll
            for (int mt = 0; mt < 4; mt++)
#pragma unroll
                for (int nt = 0; nt < 4; nt++)
                    MMA_TF32(c[mt][nt], a[mt], b[nt]);
        }
    }

    if (EPI == 3) {
#pragma unroll
        for (int mt = 0; mt < 4; mt++)
#pragma unroll
            for (int h = 0; h < 2; h++) {
                int row = bm + wm + mt * 16 + (lane >> 2) + h * 8;
                int win = row / NTOK, t = row % NTOK;
                float* dst;
                const float* xsrc = nullptr;
                if (t == 0) {
                    dst = gtout + (size_t)win * C_;
                } else {
                    int l = unscatter_l(win, t);
                    dst  = Cd  + (size_t)l * C_;
                    xsrc = res + (size_t)l * C_;
                }
#pragma unroll
                for (int nt = 0; nt < 4; nt++) {
                    int col = bn + wn + nt * 8 + 2 * (lane & 3);
                    float2 bb = *(const float2*)&bias[col];
                    float2 v;
                    v.x = c[mt][nt][2 * h]     + bb.x;
                    v.y = c[mt][nt][2 * h + 1] + bb.y;
                    if (xsrc) {
                        float2 rv = *(const float2*)&xsrc[col];
                        v.x += rv.x; v.y += rv.y;
                    }
                    *(float2*)&dst[col] = v;
                }
            }
    } else {
#pragma unroll
        for (int nt = 0; nt < 4; nt++) {
            int col = bn + wn + nt * 8 + 2 * (lane & 3);
            float2 bb = *(const float2*)&bias[col];
#pragma unroll
            for (int mt = 0; mt < 4; mt++) {
                int row0 = bm + wm + mt * 16 + (lane >> 2);
#pragma unroll
                for (int h = 0; h < 2; h++) {
                    int row = row0 + h * 8;
                    if (row < Mstore) {
                        float2 v;
                        v.x = c[mt][nt][2 * h]     + bb.x;
                        v.y = c[mt][nt][2 * h + 1] + bb.y;
                        if (EPI == 1) { v.x = gelu_f(v.x); v.y = gelu_f(v.y); }
                        size_t o = (size_t)row * N + col;
                        if (EPI == 2) {
                            float2 rv = *(const float2*)&res[o];
                            v.x += rv.x; v.y += rv.y;
                        }
                        if (CVT) { v.x = tf32r(v.x); v.y = tf32r(v.y); }
                        *(float2*)&Cd[o] = v;
                    }
                }
            }
        }
    }
}

/* ---------------- launch ------------------------------------------------ */
extern "C" void kernel_launch(void* const* d_in, const int* in_sizes, int n_in,
                              void* d_out, int out_size) {
    const float* x     = (const float*)d_in[0];
    const float* gt    = (const float*)d_in[1];
    const float* n1g   = (const float*)d_in[2];
    const float* n1b   = (const float*)d_in[3];
    const float* qkvw  = (const float*)d_in[4];
    const float* qkvb  = (const float*)d_in[5];
    const float* btab  = (const float*)d_in[6];
    const float* projw = (const float*)d_in[7];
    const float* projb = (const float*)d_in[8];
    const float* n2g   = (const float*)d_in[9];
    const float* n2b   = (const float*)d_in[10];
    const float* fc1w  = (const float*)d_in[11];
    const float* fc1b  = (const float*)d_in[12];
    const float* fc2w  = (const float*)d_in[13];
    const float* fc2b  = (const float*)d_in[14];
    float* out = (float*)d_out;

    float *xc, *qkv, *ao, *xres, *ln2b, *hb;
    float *wq, *wp, *w1, *w2;
    cudaGetSymbolAddress((void**)&xc,   g_xc);
    cudaGetSymbolAddress((void**)&qkv,  g_qkv);
    cudaGetSymbolAddress((void**)&ao,   g_attnout);
    cudaGetSymbolAddress((void**)&xres, g_xres);
    cudaGetSymbolAddress((void**)&ln2b, g_ln2);
    cudaGetSymbolAddress((void**)&hb,   g_hid);
    cudaGetSymbolAddress((void**)&wq,   g_wqkv);
    cudaGetSymbolAddress((void**)&wp,   g_wproj);
    cudaGetSymbolAddress((void**)&w1,   g_wfc1);
    cudaGetSymbolAddress((void**)&w2,   g_wfc2);

    cudaFuncSetAttribute(attn_mma,
                         cudaFuncAttributeMaxDynamicSharedMemorySize,
                         ATT2_SMEM);
    cudaFuncSetAttribute(gemm_tc<0, 0>,
                         cudaFuncAttributeMaxDynamicSharedMemorySize,
                         GEMM_SMEM_BYTES);
    cudaFuncSetAttribute(gemm_tc<1, 1>,
                         cudaFuncAttributeMaxDynamicSharedMemorySize,
                         GEMM_SMEM_BYTES);
    cudaFuncSetAttribute(gemm_tc<2, 0>,
                         cudaFuncAttributeMaxDynamicSharedMemorySize,
                         GEMM_SMEM_BYTES);
    cudaFuncSetAttribute(gemm_tc<3, 0>,
                         cudaFuncAttributeMaxDynamicSharedMemorySize,
                         GEMM_SMEM_BYTES);

    /* weight transpose + tf32 round: W^T [N][K] */
    dim3 tb(32, 8);
    wtrans<<<dim3((3 * C_) / 32, C_ / 32), tb>>>(qkvw, wq, C_, 3 * C_);
    wtrans<<<dim3(C_ / 32, C_ / 32),       tb>>>(projw, wp, C_, C_);
    wtrans<<<dim3(HID / 32, C_ / 32),      tb>>>(fc1w, w1, C_, HID);
    wtrans<<<dim3(C_ / 32, HID / 32),      tb>>>(fc2w, w2, HID, C_);

    bias_pre   <<<(NWIN * NWIN + 255) / 256, 256>>>(btab);
    gt_copy    <<<(NW * C_ + 255) / 256, 256>>>(gt);
    ln1_scatter<<<L_ / 8, 256>>>(x, n1g, n1b);

    gemm_tc<0, 0><<<dim3((3 * C_) / 128, M1 / 128), 256, GEMM_SMEM_BYTES>>>(
        xc, wq, qkvb, nullptr, qkv, nullptr, M1, 3 * C_, C_);

    attn_mma<<<NW * HEADS, 256, ATT2_SMEM>>>();

    gemm_tc<3, 0><<<dim3(C_ / 128, M1 / 128), 256, GEMM_SMEM_BYTES>>>(
        ao, wp, projb, x, xres, out + (size_t)L_ * C_, M1, C_, C_);

    ln2_kernel<<<L_ / 8, 256>>>(n2g, n2b);

    gemm_tc<1, 1><<<dim3(HID / 128, M1 / 128), 256, GEMM_SMEM_BYTES>>>(
        ln2b, w1, fc1b, nullptr, hb, nullptr, M1, HID, C_);

    gemm_tc<2, 0><<<dim3(C_ / 128, M1 / 128), 256, GEMM_SMEM_BYTES>>>(
        hb, w2, fc2b, xres, out, nullptr, L_, C_, HID);
}